// round 14
// baseline (speedup 1.0000x reference)
#include <cuda_runtime.h>
#include <cuda_bf16.h>
#include <cstdint>

// ---------------- problem constants ----------------
#define N0v 200000
#define N1v 100000
#define N2v 80000
#define K5v 125
#define K3v 27
#define M1v 20000
#define M2v 20000
#define M3v 30000
#define M4v 20000
#define EPSv 1e-5f

// ---------------- scratch ----------------
__device__ float g_buf1[N1v * 32];
__device__ float g_buf2[N1v * 32];
__device__ float g_buf3[N2v * 64];
__device__ float g_buf4[N2v * 128];
__device__ float g_buf5[N2v * 256];
__device__ float g_sum[256];
__device__ float g_sumsq[256];

#define OFF_W1B 0
#define OFF_W1C 32000
#define OFF_W2  64000
#define OFF_W3A 77824
#define OFF_W3B 133120
#define WFRAG_U4 354304
__device__ __align__(16) __nv_bfloat16 g_wfrag[WFRAG_U4 * 8];

// ---------------- helpers ----------------
__device__ __forceinline__ void red4(float* p, float a, float b, float c, float d) {
    asm volatile("red.global.add.v4.f32 [%0], {%1,%2,%3,%4};"
                 :: "l"(p), "f"(a), "f"(b), "f"(c), "f"(d) : "memory");
}

__device__ __forceinline__ void mma16(float* d, const uint32_t* a, uint32_t b0, uint32_t b1) {
    asm volatile(
        "mma.sync.aligned.m16n8k16.row.col.f32.bf16.bf16.f32 "
        "{%0,%1,%2,%3}, {%4,%5,%6,%7}, {%8,%9}, {%0,%1,%2,%3};"
        : "+f"(d[0]), "+f"(d[1]), "+f"(d[2]), "+f"(d[3])
        : "r"(a[0]), "r"(a[1]), "r"(a[2]), "r"(a[3]), "r"(b0), "r"(b1));
}

__device__ __forceinline__ void ldsm4(uint32_t* r, uint32_t addr) {
    asm volatile("ldmatrix.sync.aligned.m8n8.x4.shared.b16 {%0,%1,%2,%3}, [%4];"
                 : "=r"(r[0]), "=r"(r[1]), "=r"(r[2]), "=r"(r[3]) : "r"(addr));
}

__device__ __forceinline__ void split4(float4 v, uint2* dh, uint2* dl) {
    __nv_bfloat162 h01 = __floats2bfloat162_rn(v.x, v.y);
    __nv_bfloat162 h23 = __floats2bfloat162_rn(v.z, v.w);
    __nv_bfloat162 l01 = __floats2bfloat162_rn(
        v.x - __bfloat162float(h01.x), v.y - __bfloat162float(h01.y));
    __nv_bfloat162 l23 = __floats2bfloat162_rn(
        v.z - __bfloat162float(h23.x), v.w - __bfloat162float(h23.y));
    *dh = make_uint2(*reinterpret_cast<uint32_t*>(&h01), *reinterpret_cast<uint32_t*>(&h23));
    *dl = make_uint2(*reinterpret_cast<uint32_t*>(&l01), *reinterpret_cast<uint32_t*>(&l23));
}

// ---------------- weight prep ----------------
__device__ __forceinline__ void wpack(float v, int e, int CIN, int COUT,
                                      __nv_bfloat16* frag) {
    int per = CIN * COUT;
    int k = e / per;
    int r = e - k * per;
    int ci = r / COUT;
    int co = r - ci * COUT;
    __nv_bfloat16 h = __float2bfloat16(v);
    __nv_bfloat16 l = __float2bfloat16(v - __bfloat162float(h));
    int lane = ((co & 7) << 2) | ((ci & 7) >> 1);
    size_t f4 = (((size_t)k * (CIN >> 4) + (ci >> 4)) * (COUT >> 3) + (co >> 3)) * 32 + lane;
    int within = ci & 15;
    int slot = ((within >> 3) << 1) | (within & 1);
    frag[f4 * 8 + slot] = h;
    frag[f4 * 8 + 4 + slot] = l;
}

__global__ void wprep_all(const float* __restrict__ w1b, const float* __restrict__ w1c,
                          const float* __restrict__ w2, const float* __restrict__ w3a,
                          const float* __restrict__ w3b, __nv_bfloat16* __restrict__ frag) {
    int g = blockIdx.x * blockDim.x + threadIdx.x;
    if (g < 128000)       wpack(w1b[g], g, 32, 32, frag + (size_t)OFF_W1B * 8);
    else if (g < 256000)  wpack(w1c[g - 128000], g - 128000, 32, 32, frag + (size_t)OFF_W1C * 8);
    else if (g < 311296)  wpack(w2[g - 256000], g - 256000, 32, 64, frag + (size_t)OFF_W2 * 8);
    else if (g < 532480)  wpack(w3a[g - 311296], g - 311296, 64, 128, frag + (size_t)OFF_W3A * 8);
    else if (g < 1417216) wpack(w3b[g - 532480], g - 532480, 128, 256, frag + (size_t)OFF_W3B * 8);
}

// ---------------- conv1a: CIN=1, 8 lanes per (k,m) pair ----------------
__global__ void conv1a_kernel(const float* __restrict__ x, const float* __restrict__ w,
                              const int* __restrict__ in_idx, const int* __restrict__ out_idx,
                              float* __restrict__ out, int total, int M) {
    int gid = blockIdx.x * blockDim.x + threadIdx.x;
    int pair = gid >> 3;
    if (pair >= total) return;
    int g = gid & 7;
    int k = pair / M;
    float v = x[in_idx[pair]];
    float4 wv = *reinterpret_cast<const float4*>(w + k * 32 + g * 4);
    float* dst = out + (size_t)out_idx[pair] * 32 + g * 4;
    red4(dst, v * wv.x, v * wv.y, v * wv.z, v * wv.w);
}

// ---------------- big-CIN pipelined gather-MMA-scatter ----------------
template<int CIN, int COUT, int BN, int MINB>
__global__ __launch_bounds__(256, MINB)
void spconv_mma(const float* __restrict__ feats, const __nv_bfloat16* __restrict__ wfrag,
                const int* __restrict__ in_idx, const int* __restrict__ out_idx,
                float* __restrict__ out, int M) {
    constexpr int NT  = BN / 8;
    constexpr int NTG = COUT / 8;
    constexpr int NCH = CIN / 32;
    constexpr uint32_t BUFSTRIDE = 128 * 20 * 4;

    __shared__ uint32_t As_h[2][128][20];
    __shared__ uint32_t As_l[2][128][20];

    const int k    = blockIdx.z;
    const int m0   = blockIdx.x * 128;
    const int n0   = blockIdx.y * BN;
    const int tid  = threadIdx.x;
    const int wid  = tid >> 5;
    const int lane = tid & 31;

    const int mrow = tid >> 1;
    const int half = tid & 1;
    const int m    = m0 + mrow;
    const int frow = (m < M) ? in_idx[k * M + m] : -1;
    const float* fbase = (frow >= 0) ? (feats + (size_t)frow * CIN + half * 16) : feats;

    float acc[NT][4];
#pragma unroll
    for (int nt = 0; nt < NT; nt++) {
        acc[nt][0] = 0.f; acc[nt][1] = 0.f; acc[nt][2] = 0.f; acc[nt][3] = 0.f;
    }

    const uint4* wbase = reinterpret_cast<const uint4*>(wfrag)
                       + ((size_t)k * (CIN >> 4)) * NTG * 32;
    const int gr = lane >> 2;
    const int gc = lane & 3;
    const int r0 = wid * 16 + gr;

    const int lrow = wid * 16 + (lane & 15);
    const uint32_t lchunk = (lane >> 4) << 4;
    const uint32_t admH = (uint32_t)__cvta_generic_to_shared(&As_h[0][lrow][0]) + lchunk;
    const uint32_t admL = (uint32_t)__cvta_generic_to_shared(&As_l[0][lrow][0]) + lchunk;

    float4 pf[4];
    if (frow >= 0) {
        const float4* s = reinterpret_cast<const float4*>(fbase);
        pf[0] = s[0]; pf[1] = s[1]; pf[2] = s[2]; pf[3] = s[3];
    }
    {
        uint2* dh = reinterpret_cast<uint2*>(&As_h[0][mrow][half * 8]);
        uint2* dl = reinterpret_cast<uint2*>(&As_l[0][mrow][half * 8]);
        if (frow >= 0) {
#pragma unroll
            for (int q = 0; q < 4; q++) split4(pf[q], dh + q, dl + q);
        } else {
            uint2 z = make_uint2(0u, 0u);
#pragma unroll
            for (int q = 0; q < 4; q++) { dh[q] = z; dl[q] = z; }
        }
    }
    __syncthreads();

#pragma unroll
    for (int c = 0; c < NCH; c++) {
        const int cb = c & 1;
        if (c + 1 < NCH && frow >= 0) {
            const float4* s = reinterpret_cast<const float4*>(fbase + (c + 1) * 32);
            pf[0] = s[0]; pf[1] = s[1]; pf[2] = s[2]; pf[3] = s[3];
        }

#pragma unroll
        for (int s = 0; s < 2; s++) {
            uint32_t aH[4], aL[4];
            const uint32_t off = cb * BUFSTRIDE + s * 32;
            ldsm4(aH, admH + off);
            ldsm4(aL, admL + off);

            const uint4* wrow = wbase + ((size_t)(c * 2 + s) * NTG + (n0 >> 3)) * 32 + lane;
#pragma unroll
            for (int ng = 0; ng < NT; ng += 4) {
                uint4 b0 = wrow[(ng + 0) * 32];
                uint4 b1 = wrow[(ng + 1) * 32];
                uint4 b2 = wrow[(ng + 2) * 32];
                uint4 b3 = wrow[(ng + 3) * 32];
                mma16(acc[ng + 0], aH, b0.x, b0.y);
                mma16(acc[ng + 1], aH, b1.x, b1.y);
                mma16(acc[ng + 2], aH, b2.x, b2.y);
                mma16(acc[ng + 3], aH, b3.x, b3.y);
                mma16(acc[ng + 0], aL, b0.x, b0.y);
                mma16(acc[ng + 1], aL, b1.x, b1.y);
                mma16(acc[ng + 2], aL, b2.x, b2.y);
                mma16(acc[ng + 3], aL, b3.x, b3.y);
                mma16(acc[ng + 0], aH, b0.z, b0.w);
                mma16(acc[ng + 1], aH, b1.z, b1.w);
                mma16(acc[ng + 2], aH, b2.z, b2.w);
                mma16(acc[ng + 3], aH, b3.z, b3.w);
            }
        }

        if (c + 1 < NCH) {
            const int nb = (c + 1) & 1;
            uint2* dh = reinterpret_cast<uint2*>(&As_h[nb][mrow][half * 8]);
            uint2* dl = reinterpret_cast<uint2*>(&As_l[nb][mrow][half * 8]);
            if (frow >= 0) {
#pragma unroll
                for (int q = 0; q < 4; q++) split4(pf[q], dh + q, dl + q);
            } else {
                uint2 z = make_uint2(0u, 0u);
#pragma unroll
                for (int q = 0; q < 4; q++) { dh[q] = z; dl[q] = z; }
            }
            __syncthreads();
        }
    }

    const int mA = m0 + r0;
    const int mB = mA + 8;
    const int oA = (mA < M) ? out_idx[k * M + mA] : -1;
    const int oB = (mB < M) ? out_idx[k * M + mB] : -1;
    float* dA0 = out + (oA >= 0 ? (size_t)oA * COUT : 0) + n0;
    float* dB0 = out + (oB >= 0 ? (size_t)oB * COUT : 0) + n0;
    const bool even = (gc & 1) == 0;

#pragma unroll
    for (int nt = 0; nt < NT; nt += 2) {
        float sA0 = even ? acc[nt + 1][0] : acc[nt][0];
        float sA1 = even ? acc[nt + 1][1] : acc[nt][1];
        float sB0 = even ? acc[nt + 1][2] : acc[nt][2];
        float sB1 = even ? acc[nt + 1][3] : acc[nt][3];
        float rA0 = __shfl_xor_sync(0xffffffffu, sA0, 1);
        float rA1 = __shfl_xor_sync(0xffffffffu, sA1, 1);
        float rB0 = __shfl_xor_sync(0xffffffffu, sB0, 1);
        float rB1 = __shfl_xor_sync(0xffffffffu, sB1, 1);
        int myt = even ? nt : nt + 1;
        int cbase = myt * 8 + (even ? 2 * gc : 2 * gc - 2);
        float a0 = even ? acc[nt][0] : rA0;
        float a1 = even ? acc[nt][1] : rA1;
        float a2 = even ? rA0 : acc[nt + 1][0];
        float a3 = even ? rA1 : acc[nt + 1][1];
        float b0 = even ? acc[nt][2] : rB0;
        float b1 = even ? acc[nt][3] : rB1;
        float b2 = even ? rB0 : acc[nt + 1][2];
        float b3 = even ? rB1 : acc[nt + 1][3];
        if (oA >= 0) red4(dA0 + cbase, a0, a1, a2, a3);
        if (oB >= 0) red4(dB0 + cbase, b0, b1, b2, b3);
    }
}

// ---------------- conv3b: BM=64, full COUT=256 per CTA ----------------
__global__ __launch_bounds__(256, 2)
void spconv_b64(const float* __restrict__ feats, const __nv_bfloat16* __restrict__ wfrag,
                const int* __restrict__ in_idx, const int* __restrict__ out_idx,
                float* __restrict__ out, int M) {
    constexpr int CIN = 128, COUT = 256;
    constexpr int NT  = 16;
    constexpr int NTG = COUT / 8;
    constexpr int NCH = CIN / 32;
    constexpr uint32_t BUFSTRIDE = 64 * 20 * 4;

    __shared__ uint32_t As_h[2][64][20];
    __shared__ uint32_t As_l[2][64][20];

    const int k    = blockIdx.z;
    const int m0   = blockIdx.x * 64;
    const int tid  = threadIdx.x;
    const int wid  = tid >> 5;
    const int lane = tid & 31;

    const int mrow = tid >> 2;
    const int q    = tid & 3;
    const int m    = m0 + mrow;
    const int frow = (m < M) ? in_idx[k * M + m] : -1;
    const float* fbase = (frow >= 0) ? (feats + (size_t)frow * CIN + q * 8) : feats;

    const int mt = wid & 3;
    const int nh = wid >> 2;

    float acc[NT][4];
#pragma unroll
    for (int nt = 0; nt < NT; nt++) {
        acc[nt][0] = 0.f; acc[nt][1] = 0.f; acc[nt][2] = 0.f; acc[nt][3] = 0.f;
    }

    const uint4* wbase = reinterpret_cast<const uint4*>(wfrag)
                       + ((size_t)k * (CIN >> 4)) * NTG * 32;
    const int gr = lane >> 2;
    const int gc = lane & 3;

    const int lrow = mt * 16 + (lane & 15);
    const uint32_t lchunk = (lane >> 4) << 4;
    const uint32_t admH = (uint32_t)__cvta_generic_to_shared(&As_h[0][lrow][0]) + lchunk;
    const uint32_t admL = (uint32_t)__cvta_generic_to_shared(&As_l[0][lrow][0]) + lchunk;

    float4 pf[2];
    if (frow >= 0) {
        const float4* s = reinterpret_cast<const float4*>(fbase);
        pf[0] = s[0]; pf[1] = s[1];
    }
    {
        uint2* dh = reinterpret_cast<uint2*>(&As_h[0][mrow][q * 4]);
        uint2* dl = reinterpret_cast<uint2*>(&As_l[0][mrow][q * 4]);
        if (frow >= 0) {
            split4(pf[0], dh, dl);
            split4(pf[1], dh + 1, dl + 1);
        } else {
            uint2 z = make_uint2(0u, 0u);
            dh[0] = z; dh[1] = z; dl[0] = z; dl[1] = z;
        }
    }
    __syncthreads();

#pragma unroll
    for (int c = 0; c < NCH; c++) {
        const int cb = c & 1;
        if (c + 1 < NCH && frow >= 0) {
            const float4* s = reinterpret_cast<const float4*>(fbase + (c + 1) * 32);
            pf[0] = s[0]; pf[1] = s[1];
        }

#pragma unroll
        for (int s = 0; s < 2; s++) {
            uint32_t aH[4], aL[4];
            const uint32_t off = cb * BUFSTRIDE + s * 32;
            ldsm4(aH, admH + off);
            ldsm4(aL, admL + off);

            const uint4* wrow = wbase + ((size_t)(c * 2 + s) * NTG + nh * 16) * 32 + lane;
#pragma unroll
            for (int ng = 0; ng < NT; ng += 4) {
                uint4 b0 = wrow[(ng + 0) * 32];
                uint4 b1 = wrow[(ng + 1) * 32];
                uint4 b2 = wrow[(ng + 2) * 32];
                uint4 b3 = wrow[(ng + 3) * 32];
                mma16(acc[ng + 0], aH, b0.x, b0.y);
                mma16(acc[ng + 1], aH, b1.x, b1.y);
                mma16(acc[ng + 2], aH, b2.x, b2.y);
                mma16(acc[ng + 3], aH, b3.x, b3.y);
                mma16(acc[ng + 0], aL, b0.x, b0.y);
                mma16(acc[ng + 1], aL, b1.x, b1.y);
                mma16(acc[ng + 2], aL, b2.x, b2.y);
                mma16(acc[ng + 3], aL, b3.x, b3.y);
                mma16(acc[ng + 0], aH, b0.z, b0.w);
                mma16(acc[ng + 1], aH, b1.z, b1.w);
                mma16(acc[ng + 2], aH, b2.z, b2.w);
                mma16(acc[ng + 3], aH, b3.z, b3.w);
            }
        }

        if (c + 1 < NCH) {
            const int nb = (c + 1) & 1;
            uint2* dh = reinterpret_cast<uint2*>(&As_h[nb][mrow][q * 4]);
            uint2* dl = reinterpret_cast<uint2*>(&As_l[nb][mrow][q * 4]);
            if (frow >= 0) {
                split4(pf[0], dh, dl);
                split4(pf[1], dh + 1, dl + 1);
            } else {
                uint2 z = make_uint2(0u, 0u);
                dh[0] = z; dh[1] = z; dl[0] = z; dl[1] = z;
            }
            __syncthreads();
        }
    }

    const int mA = m0 + mt * 16 + gr;
    const int mB = mA + 8;
    const int oA = (mA < M) ? out_idx[k * M + mA] : -1;
    const int oB = (mB < M) ? out_idx[k * M + mB] : -1;
    float* dA0 = out + (oA >= 0 ? (size_t)oA * COUT : 0) + nh * 128;
    float* dB0 = out + (oB >= 0 ? (size_t)oB * COUT : 0) + nh * 128;
    const bool even = (gc & 1) == 0;

#pragma unroll
    for (int nt = 0; nt < NT; nt += 2) {
        float sA0 = even ? acc[nt + 1][0] : acc[nt][0];
        float sA1 = even ? acc[nt + 1][1] : acc[nt][1];
        float sB0 = even ? acc[nt + 1][2] : acc[nt][2];
        float sB1 = even ? acc[nt + 1][3] : acc[nt][3];
        float rA0 = __shfl_xor_sync(0xffffffffu, sA0, 1);
        float rA1 = __shfl_xor_sync(0xffffffffu, sA1, 1);
        float rB0 = __shfl_xor_sync(0xffffffffu, sB0, 1);
        float rB1 = __shfl_xor_sync(0xffffffffu, sB1, 1);
        int myt = even ? nt : nt + 1;
        int cbase = myt * 8 + (even ? 2 * gc : 2 * gc - 2);
        float a0 = even ? acc[nt][0] : rA0;
        float a1 = even ? acc[nt][1] : rA1;
        float a2 = even ? rA0 : acc[nt + 1][0];
        float a3 = even ? rA1 : acc[nt + 1][1];
        float b0 = even ? acc[nt][2] : rB0;
        float b1 = even ? acc[nt][3] : rB1;
        float b2 = even ? rB0 : acc[nt + 1][2];
        float b3 = even ? rB1 : acc[nt + 1][3];
        if (oA >= 0) red4(dA0 + cbase, a0, a1, a2, a3);
        if (oB >= 0) red4(dB0 + cbase, b0, b1, b2, b3);
    }
}

// ---------------- elementwise / BN kernels ----------------
__global__ void relu_kernel(float* __restrict__ x, int n4) {
    int i = blockIdx.x * blockDim.x + threadIdx.x;
    if (i >= n4) return;
    float4 v = reinterpret_cast<float4*>(x)[i];
    v.x = fmaxf(v.x, 0.f); v.y = fmaxf(v.y, 0.f);
    v.z = fmaxf(v.z, 0.f); v.w = fmaxf(v.w, 0.f);
    reinterpret_cast<float4*>(x)[i] = v;
}

template<int C>
__global__ void bn_stats4(const float* __restrict__ x, int rows) {
    constexpr int CG = C / 4;
    constexpr int RPB = 256 / CG;
    const int cg  = threadIdx.x & (CG - 1);
    const int rsub = threadIdx.x / CG;
    float s0 = 0.f, s1 = 0.f, s2 = 0.f, s3 = 0.f;
    float q0 = 0.f, q1 = 0.f, q2 = 0.f, q3 = 0.f;
    for (int r = blockIdx.x * RPB + rsub; r < rows; r += gridDim.x * RPB) {
        float4 v = *reinterpret_cast<const float4*>(x + (size_t)r * C + cg * 4);
        s0 += v.x; q0 += v.x * v.x;
        s1 += v.y; q1 += v.y * v.y;
        s2 += v.z; q2 += v.z * v.z;
        s3 += v.w; q3 += v.w * v.w;
    }
    __shared__ float ss[256][4], sq[256][4];
    ss[threadIdx.x][0] = s0; ss[threadIdx.x][1] = s1;
    ss[threadIdx.x][2] = s2; ss[threadIdx.x][3] = s3;
    sq[threadIdx.x][0] = q0; sq[threadIdx.x][1] = q1;
    sq[threadIdx.x][2] = q2; sq[threadIdx.x][3] = q3;
    __syncthreads();
    if (threadIdx.x < C) {
        int mycg = threadIdx.x >> 2;
        int j = threadIdx.x & 3;
        float s = 0.f, q = 0.f;
        for (int t = mycg; t < 256; t += CG) { s += ss[t][j]; q += sq[t][j]; }
        atomicAdd(&g_sum[threadIdx.x], s);
        atomicAdd(&g_sumsq[threadIdx.x], q);
    }
}

__global__ void bn_relu_kernel(const float* __restrict__ x, float* __restrict__ y,
                               const float* __restrict__ gg, const float* __restrict__ bb,
                               float invN, int total, int cmask) {
    int e = blockIdx.x * blockDim.x + threadIdx.x;
    if (e >= total) return;
    int c = e & cmask;
    float mean = g_sum[c] * invN;
    float var  = g_sumsq[c] * invN - mean * mean;
    float s = rsqrtf(var + EPSv) * gg[c];
    float v = (x[e] - mean) * s + bb[c];
    y[e] = fmaxf(v, 0.f);
}

// ---------------- orchestration ----------------
extern "C" void kernel_launch(void* const* d_in, const int* in_sizes, int n_in,
                              void* d_out, int out_size) {
    const float* x_feats = (const float*)d_in[0];
    const float* w1a = (const float*)d_in[1];
    const float* w1b = (const float*)d_in[2];
    const float* w1c = (const float*)d_in[3];
    const float* w2  = (const float*)d_in[4];
    const float* w3a = (const float*)d_in[5];
    const float* w3b = (const float*)d_in[6];
    const float* bn1b_g = (const float*)d_in[7];
    const float* bn1b_b = (const float*)d_in[8];
    const float* bn1c_g = (const float*)d_in[9];
    const float* bn1c_b = (const float*)d_in[10];
    const float* bn3a_g = (const float*)d_in[11];
    const float* bn3a_b = (const float*)d_in[12];
    const float* bn3b_g = (const float*)d_in[13];
    const float* bn3b_b = (const float*)d_in[14];
    const int* km1a_in  = (const int*)d_in[15];
    const int* km1a_out = (const int*)d_in[16];
    const int* km1b_in  = (const int*)d_in[17];
    const int* km1b_out = (const int*)d_in[18];
    const int* km1c_in  = (const int*)d_in[19];
    const int* km1c_out = (const int*)d_in[20];
    const int* km2_in   = (const int*)d_in[21];
    const int* km2_out  = (const int*)d_in[22];
    const int* km3a_in  = (const int*)d_in[23];
    const int* km3a_out = (const int*)d_in[24];
    const int* km3b_in  = (const int*)d_in[25];
    const int* km3b_out = (const int*)d_in[26];

    float* out = (float*)d_out;
    float* x_e1 = out;
    float* x_e2 = out + (size_t)N1v * 32;

    float *buf1, *buf2, *buf3, *buf4, *buf5, *gsum, *gsq;
    __nv_bfloat16* wf;
    cudaGetSymbolAddress((void**)&buf1, g_buf1);
    cudaGetSymbolAddress((void**)&buf2, g_buf2);
    cudaGetSymbolAddress((void**)&buf3, g_buf3);
    cudaGetSymbolAddress((void**)&buf4, g_buf4);
    cudaGetSymbolAddress((void**)&buf5, g_buf5);
    cudaGetSymbolAddress((void**)&gsum, g_sum);
    cudaGetSymbolAddress((void**)&gsq, g_sumsq);
    cudaGetSymbolAddress((void**)&wf, g_wfrag);

    wprep_all<<<(1417216 + 255) / 256, 256>>>(w1b, w1c, w2, w3a, w3b, wf);

    const int SG = 1024;

    // ---- enc1a: conv(1->32, k5) + relu ----
    cudaMemsetAsync(buf1, 0, (size_t)N1v * 32 * sizeof(float), 0);
    {
        int total = K5v * M1v;
        conv1a_kernel<<<(total * 8 + 255) / 256, 256>>>(x_feats, w1a, km1a_in, km1a_out, buf1, total, M1v);
        relu_kernel<<<(N1v * 32 / 4 + 255) / 256, 256>>>(buf1, N1v * 32 / 4);
    }

    // ---- enc1b: conv(32->32, k5) + BN + relu ----
    cudaMemsetAsync(buf2, 0, (size_t)N1v * 32 * sizeof(float), 0);
    spconv_mma<32, 32, 32, 4><<<dim3((M2v + 127) / 128, 1, K5v), 256>>>(
        buf1, wf + (size_t)OFF_W1B * 8, km1b_in, km1b_out, buf2, M2v);
    cudaMemsetAsync(gsum, 0, 256 * sizeof(float), 0);
    cudaMemsetAsync(gsq, 0, 256 * sizeof(float), 0);
    bn_stats4<32><<<SG, 256>>>(buf2, N1v);
    bn_relu_kernel<<<(N1v * 32 + 255) / 256, 256>>>(buf2, buf1, bn1b_g, bn1b_b, 1.0f / N1v, N1v * 32, 31);

    // ---- enc1c: conv(32->32, k5) + BN + relu -> x_e1 ----
    cudaMemsetAsync(buf2, 0, (size_t)N1v * 32 * sizeof(float), 0);
    spconv_mma<32, 32, 32, 4><<<dim3((M2v + 127) / 128, 1, K5v), 256>>>(
        buf1, wf + (size_t)OFF_W1C * 8, km1c_in, km1c_out, buf2, M2v);
    cudaMemsetAsync(gsum, 0, 256 * sizeof(float), 0);
    cudaMemsetAsync(gsq, 0, 256 * sizeof(float), 0);
    bn_stats4<32><<<SG, 256>>>(buf2, N1v);
    bn_relu_kernel<<<(N1v * 32 + 255) / 256, 256>>>(buf2, x_e1, bn1c_g, bn1c_b, 1.0f / N1v, N1v * 32, 31);

    // ---- conv2: conv(32->64, k3), no activation ----
    cudaMemsetAsync(buf3, 0, (size_t)N2v * 64 * sizeof(float), 0);
    spconv_mma<32, 64, 64, 4><<<dim3((M3v + 127) / 128, 1, K3v), 256>>>(
        x_e1, wf + (size_t)OFF_W2 * 8, km2_in, km2_out, buf3, M3v);

    // ---- enc2a: conv(64->128, k3) + BN + relu ----
    cudaMemsetAsync(buf4, 0, (size_t)N2v * 128 * sizeof(float), 0);
    spconv_mma<64, 128, 128, 2><<<dim3((M4v + 127) / 128, 1, K3v), 256>>>(
        buf3, wf + (size_t)OFF_W3A * 8, km3a_in, km3a_out, buf4, M4v);
    cudaMemsetAsync(gsum, 0, 256 * sizeof(float), 0);
    cudaMemsetAsync(gsq, 0, 256 * sizeof(float), 0);
    bn_stats4<128><<<SG, 256>>>(buf4, N2v);
    bn_relu_kernel<<<(N2v * 128 + 255) / 256, 256>>>(buf4, buf4, bn3a_g, bn3a_b, 1.0f / N2v, N2v * 128, 127);

    // ---- enc2b: conv(128->256, k3) + BN + relu -> x_e2 ----
    cudaMemsetAsync(buf5, 0, (size_t)N2v * 256 * sizeof(float), 0);
    spconv_b64<<<dim3((M4v + 63) / 64, 1, K3v), 256>>>(
        buf4, wf + (size_t)OFF_W3B * 8, km3b_in, km3b_out, buf5, M4v);
    cudaMemsetAsync(gsum, 0, 256 * sizeof(float), 0);
    cudaMemsetAsync(gsq, 0, 256 * sizeof(float), 0);
    bn_stats4<256><<<SG, 256>>>(buf5, N2v);
    bn_relu_kernel<<<(N2v * 256 + 255) / 256, 256>>>(buf5, x_e2, bn3b_g, bn3b_b, 1.0f / N2v, N2v * 256, 255);
}

// round 15
// speedup vs baseline: 1.4464x; 1.4464x over previous
#include <cuda_runtime.h>
#include <cuda_bf16.h>
#include <cstdint>

// ---------------- problem constants ----------------
#define N0v 200000
#define N1v 100000
#define N2v 80000
#define K5v 125
#define K3v 27
#define M1v 20000
#define M2v 20000
#define M3v 30000
#define M4v 20000
#define EPSv 1e-5f

// ---------------- scratch ----------------
__device__ float g_buf1[N1v * 32];
__device__ float g_buf2[N1v * 32];
__device__ float g_buf3[N2v * 64];
__device__ float g_buf4[N2v * 128];
__device__ float g_buf5[N2v * 256];
__device__ float g_sum[256];
__device__ float g_sumsq[256];

#define OFF_W1B 0
#define OFF_W1C 32000
#define OFF_W2  64000
#define OFF_W3A 77824
#define OFF_W3B 133120
#define WFRAG_U4 354304
__device__ __align__(16) __nv_bfloat16 g_wfrag[WFRAG_U4 * 8];

// ---------------- helpers ----------------
__device__ __forceinline__ void red4(float* p, float a, float b, float c, float d) {
    asm volatile("red.global.add.v4.f32 [%0], {%1,%2,%3,%4};"
                 :: "l"(p), "f"(a), "f"(b), "f"(c), "f"(d) : "memory");
}

__device__ __forceinline__ void mma16(float* d, const uint32_t* a, uint32_t b0, uint32_t b1) {
    asm volatile(
        "mma.sync.aligned.m16n8k16.row.col.f32.bf16.bf16.f32 "
        "{%0,%1,%2,%3}, {%4,%5,%6,%7}, {%8,%9}, {%0,%1,%2,%3};"
        : "+f"(d[0]), "+f"(d[1]), "+f"(d[2]), "+f"(d[3])
        : "r"(a[0]), "r"(a[1]), "r"(a[2]), "r"(a[3]), "r"(b0), "r"(b1));
}

__device__ __forceinline__ void ldsm4(uint32_t* r, uint32_t addr) {
    asm volatile("ldmatrix.sync.aligned.m8n8.x4.shared.b16 {%0,%1,%2,%3}, [%4];"
                 : "=r"(r[0]), "=r"(r[1]), "=r"(r[2]), "=r"(r[3]) : "r"(addr));
}

__device__ __forceinline__ void split4(float4 v, uint2* dh, uint2* dl) {
    __nv_bfloat162 h01 = __floats2bfloat162_rn(v.x, v.y);
    __nv_bfloat162 h23 = __floats2bfloat162_rn(v.z, v.w);
    __nv_bfloat162 l01 = __floats2bfloat162_rn(
        v.x - __bfloat162float(h01.x), v.y - __bfloat162float(h01.y));
    __nv_bfloat162 l23 = __floats2bfloat162_rn(
        v.z - __bfloat162float(h23.x), v.w - __bfloat162float(h23.y));
    *dh = make_uint2(*reinterpret_cast<uint32_t*>(&h01), *reinterpret_cast<uint32_t*>(&h23));
    *dl = make_uint2(*reinterpret_cast<uint32_t*>(&l01), *reinterpret_cast<uint32_t*>(&l23));
}

// ---------------- weight prep ----------------
__device__ __forceinline__ void wpack(float v, int e, int CIN, int COUT,
                                      __nv_bfloat16* frag) {
    int per = CIN * COUT;
    int k = e / per;
    int r = e - k * per;
    int ci = r / COUT;
    int co = r - ci * COUT;
    __nv_bfloat16 h = __float2bfloat16(v);
    __nv_bfloat16 l = __float2bfloat16(v - __bfloat162float(h));
    int lane = ((co & 7) << 2) | ((ci & 7) >> 1);
    size_t f4 = (((size_t)k * (CIN >> 4) + (ci >> 4)) * (COUT >> 3) + (co >> 3)) * 32 + lane;
    int within = ci & 15;
    int slot = ((within >> 3) << 1) | (within & 1);
    frag[f4 * 8 + slot] = h;
    frag[f4 * 8 + 4 + slot] = l;
}

__global__ void wprep_all(const float* __restrict__ w1b, const float* __restrict__ w1c,
                          const float* __restrict__ w2, const float* __restrict__ w3a,
                          const float* __restrict__ w3b, __nv_bfloat16* __restrict__ frag) {
    int g = blockIdx.x * blockDim.x + threadIdx.x;
    if (g < 128000)       wpack(w1b[g], g, 32, 32, frag + (size_t)OFF_W1B * 8);
    else if (g < 256000)  wpack(w1c[g - 128000], g - 128000, 32, 32, frag + (size_t)OFF_W1C * 8);
    else if (g < 311296)  wpack(w2[g - 256000], g - 256000, 32, 64, frag + (size_t)OFF_W2 * 8);
    else if (g < 532480)  wpack(w3a[g - 311296], g - 311296, 64, 128, frag + (size_t)OFF_W3A * 8);
    else if (g < 1417216) wpack(w3b[g - 532480], g - 532480, 128, 256, frag + (size_t)OFF_W3B * 8);
}

// ---------------- conv1a: CIN=1, 8 lanes per (k,m) pair ----------------
__global__ void conv1a_kernel(const float* __restrict__ x, const float* __restrict__ w,
                              const int* __restrict__ in_idx, const int* __restrict__ out_idx,
                              float* __restrict__ out, int total, int M) {
    int gid = blockIdx.x * blockDim.x + threadIdx.x;
    int pair = gid >> 3;
    if (pair >= total) return;
    int g = gid & 7;
    int k = pair / M;
    float v = x[in_idx[pair]];
    float4 wv = *reinterpret_cast<const float4*>(w + k * 32 + g * 4);
    float* dst = out + (size_t)out_idx[pair] * 32 + g * 4;
    red4(dst, v * wv.x, v * wv.y, v * wv.z, v * wv.w);
}

// ---------------- big-CIN pipelined gather-MMA-scatter (R13 exact) ----------------
template<int CIN, int COUT, int BN, int MINB>
__global__ __launch_bounds__(256, MINB)
void spconv_mma(const float* __restrict__ feats, const __nv_bfloat16* __restrict__ wfrag,
                const int* __restrict__ in_idx, const int* __restrict__ out_idx,
                float* __restrict__ out, int M) {
    constexpr int NT  = BN / 8;
    constexpr int NTG = COUT / 8;
    constexpr int NCH = CIN / 32;
    constexpr uint32_t BUFSTRIDE = 128 * 20 * 4;

    __shared__ uint32_t As_h[2][128][20];
    __shared__ uint32_t As_l[2][128][20];

    const int k    = blockIdx.z;
    const int m0   = blockIdx.x * 128;
    const int n0   = blockIdx.y * BN;
    const int tid  = threadIdx.x;
    const int wid  = tid >> 5;
    const int lane = tid & 31;

    const int mrow = tid >> 1;
    const int half = tid & 1;
    const int m    = m0 + mrow;
    const int frow = (m < M) ? in_idx[k * M + m] : -1;
    const float* fbase = (frow >= 0) ? (feats + (size_t)frow * CIN + half * 16) : feats;

    float acc[NT][4];
#pragma unroll
    for (int nt = 0; nt < NT; nt++) {
        acc[nt][0] = 0.f; acc[nt][1] = 0.f; acc[nt][2] = 0.f; acc[nt][3] = 0.f;
    }

    const uint4* wbase = reinterpret_cast<const uint4*>(wfrag)
                       + ((size_t)k * (CIN >> 4)) * NTG * 32;
    const int gr = lane >> 2;
    const int gc = lane & 3;
    const int r0 = wid * 16 + gr;

    const int lrow = wid * 16 + (lane & 15);
    const uint32_t lchunk = (lane >> 4) << 4;
    const uint32_t admH = (uint32_t)__cvta_generic_to_shared(&As_h[0][lrow][0]) + lchunk;
    const uint32_t admL = (uint32_t)__cvta_generic_to_shared(&As_l[0][lrow][0]) + lchunk;

    float4 pf[4];
    if (frow >= 0) {
        const float4* s = reinterpret_cast<const float4*>(fbase);
        pf[0] = s[0]; pf[1] = s[1]; pf[2] = s[2]; pf[3] = s[3];
    }
    {
        uint2* dh = reinterpret_cast<uint2*>(&As_h[0][mrow][half * 8]);
        uint2* dl = reinterpret_cast<uint2*>(&As_l[0][mrow][half * 8]);
        if (frow >= 0) {
#pragma unroll
            for (int q = 0; q < 4; q++) split4(pf[q], dh + q, dl + q);
        } else {
            uint2 z = make_uint2(0u, 0u);
#pragma unroll
            for (int q = 0; q < 4; q++) { dh[q] = z; dl[q] = z; }
        }
    }
    __syncthreads();

#pragma unroll
    for (int c = 0; c < NCH; c++) {
        const int cb = c & 1;
        if (c + 1 < NCH && frow >= 0) {
            const float4* s = reinterpret_cast<const float4*>(fbase + (c + 1) * 32);
            pf[0] = s[0]; pf[1] = s[1]; pf[2] = s[2]; pf[3] = s[3];
        }

#pragma unroll
        for (int s = 0; s < 2; s++) {
            uint32_t aH[4], aL[4];
            const uint32_t off = cb * BUFSTRIDE + s * 32;
            ldsm4(aH, admH + off);
            ldsm4(aL, admL + off);

            const uint4* wrow = wbase + ((size_t)(c * 2 + s) * NTG + (n0 >> 3)) * 32 + lane;
#pragma unroll
            for (int ng = 0; ng < NT; ng += 4) {
                uint4 b0 = wrow[(ng + 0) * 32];
                uint4 b1 = wrow[(ng + 1) * 32];
                uint4 b2 = wrow[(ng + 2) * 32];
                uint4 b3 = wrow[(ng + 3) * 32];
                mma16(acc[ng + 0], aH, b0.x, b0.y);
                mma16(acc[ng + 1], aH, b1.x, b1.y);
                mma16(acc[ng + 2], aH, b2.x, b2.y);
                mma16(acc[ng + 3], aH, b3.x, b3.y);
                mma16(acc[ng + 0], aL, b0.x, b0.y);
                mma16(acc[ng + 1], aL, b1.x, b1.y);
                mma16(acc[ng + 2], aL, b2.x, b2.y);
                mma16(acc[ng + 3], aL, b3.x, b3.y);
                mma16(acc[ng + 0], aH, b0.z, b0.w);
                mma16(acc[ng + 1], aH, b1.z, b1.w);
                mma16(acc[ng + 2], aH, b2.z, b2.w);
                mma16(acc[ng + 3], aH, b3.z, b3.w);
            }
        }

        if (c + 1 < NCH) {
            const int nb = (c + 1) & 1;
            uint2* dh = reinterpret_cast<uint2*>(&As_h[nb][mrow][half * 8]);
            uint2* dl = reinterpret_cast<uint2*>(&As_l[nb][mrow][half * 8]);
            if (frow >= 0) {
#pragma unroll
                for (int q = 0; q < 4; q++) split4(pf[q], dh + q, dl + q);
            } else {
                uint2 z = make_uint2(0u, 0u);
#pragma unroll
                for (int q = 0; q < 4; q++) { dh[q] = z; dl[q] = z; }
            }
            __syncthreads();
        }
    }

    const int mA = m0 + r0;
    const int mB = mA + 8;
    const int oA = (mA < M) ? out_idx[k * M + mA] : -1;
    const int oB = (mB < M) ? out_idx[k * M + mB] : -1;
    float* dA0 = out + (oA >= 0 ? (size_t)oA * COUT : 0) + n0;
    float* dB0 = out + (oB >= 0 ? (size_t)oB * COUT : 0) + n0;
    const bool even = (gc & 1) == 0;

#pragma unroll
    for (int nt = 0; nt < NT; nt += 2) {
        float sA0 = even ? acc[nt + 1][0] : acc[nt][0];
        float sA1 = even ? acc[nt + 1][1] : acc[nt][1];
        float sB0 = even ? acc[nt + 1][2] : acc[nt][2];
        float sB1 = even ? acc[nt + 1][3] : acc[nt][3];
        float rA0 = __shfl_xor_sync(0xffffffffu, sA0, 1);
        float rA1 = __shfl_xor_sync(0xffffffffu, sA1, 1);
        float rB0 = __shfl_xor_sync(0xffffffffu, sB0, 1);
        float rB1 = __shfl_xor_sync(0xffffffffu, sB1, 1);
        int myt = even ? nt : nt + 1;
        int cbase = myt * 8 + (even ? 2 * gc : 2 * gc - 2);
        float a0 = even ? acc[nt][0] : rA0;
        float a1 = even ? acc[nt][1] : rA1;
        float a2 = even ? rA0 : acc[nt + 1][0];
        float a3 = even ? rA1 : acc[nt + 1][1];
        float b0 = even ? acc[nt][2] : rB0;
        float b1 = even ? acc[nt][3] : rB1;
        float b2 = even ? rB0 : acc[nt + 1][2];
        float b3 = even ? rB1 : acc[nt + 1][3];
        if (oA >= 0) red4(dA0 + cbase, a0, a1, a2, a3);
        if (oB >= 0) red4(dB0 + cbase, b0, b1, b2, b3);
    }
}

// ---------------- conv3b: BM=64, full COUT=256 per CTA (R13 exact) ----------------
__global__ __launch_bounds__(256, 2)
void spconv_b64(const float* __restrict__ feats, const __nv_bfloat16* __restrict__ wfrag,
                const int* __restrict__ in_idx, const int* __restrict__ out_idx,
                float* __restrict__ out, int M) {
    constexpr int CIN = 128, COUT = 256;
    constexpr int NT  = 16;
    constexpr int NTG = COUT / 8;
    constexpr int NCH = CIN / 32;
    constexpr uint32_t BUFSTRIDE = 64 * 20 * 4;

    __shared__ uint32_t As_h[2][64][20];
    __shared__ uint32_t As_l[2][64][20];

    const int k    = blockIdx.z;
    const int m0   = blockIdx.x * 64;
    const int tid  = threadIdx.x;
    const int wid  = tid >> 5;
    const int lane = tid & 31;

    const int mrow = tid >> 2;
    const int q    = tid & 3;
    const int m    = m0 + mrow;
    const int frow = (m < M) ? in_idx[k * M + m] : -1;
    const float* fbase = (frow >= 0) ? (feats + (size_t)frow * CIN + q * 8) : feats;

    const int mt = wid & 3;
    const int nh = wid >> 2;

    float acc[NT][4];
#pragma unroll
    for (int nt = 0; nt < NT; nt++) {
        acc[nt][0] = 0.f; acc[nt][1] = 0.f; acc[nt][2] = 0.f; acc[nt][3] = 0.f;
    }

    const uint4* wbase = reinterpret_cast<const uint4*>(wfrag)
                       + ((size_t)k * (CIN >> 4)) * NTG * 32;
    const int gr = lane >> 2;
    const int gc = lane & 3;

    const int lrow = mt * 16 + (lane & 15);
    const uint32_t lchunk = (lane >> 4) << 4;
    const uint32_t admH = (uint32_t)__cvta_generic_to_shared(&As_h[0][lrow][0]) + lchunk;
    const uint32_t admL = (uint32_t)__cvta_generic_to_shared(&As_l[0][lrow][0]) + lchunk;

    float4 pf[2];
    if (frow >= 0) {
        const float4* s = reinterpret_cast<const float4*>(fbase);
        pf[0] = s[0]; pf[1] = s[1];
    }
    {
        uint2* dh = reinterpret_cast<uint2*>(&As_h[0][mrow][q * 4]);
        uint2* dl = reinterpret_cast<uint2*>(&As_l[0][mrow][q * 4]);
        if (frow >= 0) {
            split4(pf[0], dh, dl);
            split4(pf[1], dh + 1, dl + 1);
        } else {
            uint2 z = make_uint2(0u, 0u);
            dh[0] = z; dh[1] = z; dl[0] = z; dl[1] = z;
        }
    }
    __syncthreads();

#pragma unroll
    for (int c = 0; c < NCH; c++) {
        const int cb = c & 1;
        if (c + 1 < NCH && frow >= 0) {
            const float4* s = reinterpret_cast<const float4*>(fbase + (c + 1) * 32);
            pf[0] = s[0]; pf[1] = s[1];
        }

#pragma unroll
        for (int s = 0; s < 2; s++) {
            uint32_t aH[4], aL[4];
            const uint32_t off = cb * BUFSTRIDE + s * 32;
            ldsm4(aH, admH + off);
            ldsm4(aL, admL + off);

            const uint4* wrow = wbase + ((size_t)(c * 2 + s) * NTG + nh * 16) * 32 + lane;
#pragma unroll
            for (int ng = 0; ng < NT; ng += 4) {
                uint4 b0 = wrow[(ng + 0) * 32];
                uint4 b1 = wrow[(ng + 1) * 32];
                uint4 b2 = wrow[(ng + 2) * 32];
                uint4 b3 = wrow[(ng + 3) * 32];
                mma16(acc[ng + 0], aH, b0.x, b0.y);
                mma16(acc[ng + 1], aH, b1.x, b1.y);
                mma16(acc[ng + 2], aH, b2.x, b2.y);
                mma16(acc[ng + 3], aH, b3.x, b3.y);
                mma16(acc[ng + 0], aL, b0.x, b0.y);
                mma16(acc[ng + 1], aL, b1.x, b1.y);
                mma16(acc[ng + 2], aL, b2.x, b2.y);
                mma16(acc[ng + 3], aL, b3.x, b3.y);
                mma16(acc[ng + 0], aH, b0.z, b0.w);
                mma16(acc[ng + 1], aH, b1.z, b1.w);
                mma16(acc[ng + 2], aH, b2.z, b2.w);
                mma16(acc[ng + 3], aH, b3.z, b3.w);
            }
        }

        if (c + 1 < NCH) {
            const int nb = (c + 1) & 1;
            uint2* dh = reinterpret_cast<uint2*>(&As_h[nb][mrow][q * 4]);
            uint2* dl = reinterpret_cast<uint2*>(&As_l[nb][mrow][q * 4]);
            if (frow >= 0) {
                split4(pf[0], dh, dl);
                split4(pf[1], dh + 1, dl + 1);
            } else {
                uint2 z = make_uint2(0u, 0u);
                dh[0] = z; dh[1] = z; dl[0] = z; dl[1] = z;
            }
            __syncthreads();
        }
    }

    const int mA = m0 + mt * 16 + gr;
    const int mB = mA + 8;
    const int oA = (mA < M) ? out_idx[k * M + mA] : -1;
    const int oB = (mB < M) ? out_idx[k * M + mB] : -1;
    float* dA0 = out + (oA >= 0 ? (size_t)oA * COUT : 0) + nh * 128;
    float* dB0 = out + (oB >= 0 ? (size_t)oB * COUT : 0) + nh * 128;
    const bool even = (gc & 1) == 0;

#pragma unroll
    for (int nt = 0; nt < NT; nt += 2) {
        float sA0 = even ? acc[nt + 1][0] : acc[nt][0];
        float sA1 = even ? acc[nt + 1][1] : acc[nt][1];
        float sB0 = even ? acc[nt + 1][2] : acc[nt][2];
        float sB1 = even ? acc[nt + 1][3] : acc[nt][3];
        float rA0 = __shfl_xor_sync(0xffffffffu, sA0, 1);
        float rA1 = __shfl_xor_sync(0xffffffffu, sA1, 1);
        float rB0 = __shfl_xor_sync(0xffffffffu, sB0, 1);
        float rB1 = __shfl_xor_sync(0xffffffffu, sB1, 1);
        int myt = even ? nt : nt + 1;
        int cbase = myt * 8 + (even ? 2 * gc : 2 * gc - 2);
        float a0 = even ? acc[nt][0] : rA0;
        float a1 = even ? acc[nt][1] : rA1;
        float a2 = even ? rA0 : acc[nt + 1][0];
        float a3 = even ? rA1 : acc[nt + 1][1];
        float b0 = even ? acc[nt][2] : rB0;
        float b1 = even ? acc[nt][3] : rB1;
        float b2 = even ? rB0 : acc[nt + 1][2];
        float b3 = even ? rB1 : acc[nt + 1][3];
        if (oA >= 0) red4(dA0 + cbase, a0, a1, a2, a3);
        if (oB >= 0) red4(dB0 + cbase, b0, b1, b2, b3);
    }
}

// ---------------- elementwise / BN kernels ----------------
__global__ void relu_kernel(float* __restrict__ x, int n4) {
    int i = blockIdx.x * blockDim.x + threadIdx.x;
    if (i >= n4) return;
    float4 v = reinterpret_cast<float4*>(x)[i];
    v.x = fmaxf(v.x, 0.f); v.y = fmaxf(v.y, 0.f);
    v.z = fmaxf(v.z, 0.f); v.w = fmaxf(v.w, 0.f);
    reinterpret_cast<float4*>(x)[i] = v;
}

template<int C>
__global__ void bn_stats4(const float* __restrict__ x, int rows) {
    constexpr int CG = C / 4;
    constexpr int RPB = 256 / CG;
    const int cg  = threadIdx.x & (CG - 1);
    const int rsub = threadIdx.x / CG;
    float s0 = 0.f, s1 = 0.f, s2 = 0.f, s3 = 0.f;
    float q0 = 0.f, q1 = 0.f, q2 = 0.f, q3 = 0.f;
    for (int r = blockIdx.x * RPB + rsub; r < rows; r += gridDim.x * RPB) {
        float4 v = *reinterpret_cast<const float4*>(x + (size_t)r * C + cg * 4);
        s0 += v.x; q0 += v.x * v.x;
        s1 += v.y; q1 += v.y * v.y;
        s2 += v.z; q2 += v.z * v.z;
        s3 += v.w; q3 += v.w * v.w;
    }
    __shared__ float ss[256][4], sq[256][4];
    ss[threadIdx.x][0] = s0; ss[threadIdx.x][1] = s1;
    ss[threadIdx.x][2] = s2; ss[threadIdx.x][3] = s3;
    sq[threadIdx.x][0] = q0; sq[threadIdx.x][1] = q1;
    sq[threadIdx.x][2] = q2; sq[threadIdx.x][3] = q3;
    __syncthreads();
    if (threadIdx.x < C) {
        int mycg = threadIdx.x >> 2;
        int j = threadIdx.x & 3;
        float s = 0.f, q = 0.f;
        for (int t = mycg; t < 256; t += CG) { s += ss[t][j]; q += sq[t][j]; }
        atomicAdd(&g_sum[threadIdx.x], s);
        atomicAdd(&g_sumsq[threadIdx.x], q);
    }
}

// vectorized bn+relu: one float4 (4 channels) per thread
__global__ void bn_relu4_kernel(const float* __restrict__ x, float* __restrict__ y,
                                const float* __restrict__ gg, const float* __restrict__ bb,
                                float invN, int total4, int cmask4) {
    int e = blockIdx.x * blockDim.x + threadIdx.x;
    if (e >= total4) return;
    int cg = e & cmask4;          // float4-group within row
    float4 v = reinterpret_cast<const float4*>(x)[e];
    int c = cg * 4;
    float m0 = g_sum[c] * invN,     m1 = g_sum[c + 1] * invN;
    float m2 = g_sum[c + 2] * invN, m3 = g_sum[c + 3] * invN;
    float s0 = rsqrtf(g_sumsq[c] * invN - m0 * m0 + EPSv) * gg[c];
    float s1 = rsqrtf(g_sumsq[c + 1] * invN - m1 * m1 + EPSv) * gg[c + 1];
    float s2 = rsqrtf(g_sumsq[c + 2] * invN - m2 * m2 + EPSv) * gg[c + 2];
    float s3 = rsqrtf(g_sumsq[c + 3] * invN - m3 * m3 + EPSv) * gg[c + 3];
    v.x = fmaxf((v.x - m0) * s0 + bb[c], 0.f);
    v.y = fmaxf((v.y - m1) * s1 + bb[c + 1], 0.f);
    v.z = fmaxf((v.z - m2) * s2 + bb[c + 2], 0.f);
    v.w = fmaxf((v.w - m3) * s3 + bb[c + 3], 0.f);
    reinterpret_cast<float4*>(y)[e] = v;
}

// ---------------- orchestration (R13 exact + bn_relu4) ----------------
extern "C" void kernel_launch(void* const* d_in, const int* in_sizes, int n_in,
                              void* d_out, int out_size) {
    const float* x_feats = (const float*)d_in[0];
    const float* w1a = (const float*)d_in[1];
    const float* w1b = (const float*)d_in[2];
    const float* w1c = (const float*)d_in[3];
    const float* w2  = (const float*)d_in[4];
    const float* w3a = (const float*)d_in[5];
    const float* w3b = (const float*)d_in[6];
    const float* bn1b_g = (const float*)d_in[7];
    const float* bn1b_b = (const float*)d_in[8];
    const float* bn1c_g = (const float*)d_in[9];
    const float* bn1c_b = (const float*)d_in[10];
    const float* bn3a_g = (const float*)d_in[11];
    const float* bn3a_b = (const float*)d_in[12];
    const float* bn3b_g = (const float*)d_in[13];
    const float* bn3b_b = (const float*)d_in[14];
    const int* km1a_in  = (const int*)d_in[15];
    const int* km1a_out = (const int*)d_in[16];
    const int* km1b_in  = (const int*)d_in[17];
    const int* km1b_out = (const int*)d_in[18];
    const int* km1c_in  = (const int*)d_in[19];
    const int* km1c_out = (const int*)d_in[20];
    const int* km2_in   = (const int*)d_in[21];
    const int* km2_out  = (const int*)d_in[22];
    const int* km3a_in  = (const int*)d_in[23];
    const int* km3a_out = (const int*)d_in[24];
    const int* km3b_in  = (const int*)d_in[25];
    const int* km3b_out = (const int*)d_in[26];

    float* out = (float*)d_out;
    float* x_e1 = out;
    float* x_e2 = out + (size_t)N1v * 32;

    float *buf1, *buf2, *buf3, *buf4, *buf5, *gsum, *gsq;
    __nv_bfloat16* wf;
    cudaGetSymbolAddress((void**)&buf1, g_buf1);
    cudaGetSymbolAddress((void**)&buf2, g_buf2);
    cudaGetSymbolAddress((void**)&buf3, g_buf3);
    cudaGetSymbolAddress((void**)&buf4, g_buf4);
    cudaGetSymbolAddress((void**)&buf5, g_buf5);
    cudaGetSymbolAddress((void**)&gsum, g_sum);
    cudaGetSymbolAddress((void**)&gsq, g_sumsq);
    cudaGetSymbolAddress((void**)&wf, g_wfrag);

    wprep_all<<<(1417216 + 255) / 256, 256>>>(w1b, w1c, w2, w3a, w3b, wf);

    const int SG = 1024;

    // ---- enc1a: conv(1->32, k5) + relu ----
    cudaMemsetAsync(buf1, 0, (size_t)N1v * 32 * sizeof(float), 0);
    {
        int total = K5v * M1v;
        conv1a_kernel<<<(total * 8 + 255) / 256, 256>>>(x_feats, w1a, km1a_in, km1a_out, buf1, total, M1v);
        relu_kernel<<<(N1v * 32 / 4 + 255) / 256, 256>>>(buf1, N1v * 32 / 4);
    }

    // ---- enc1b: conv(32->32, k5) + BN + relu ----
    cudaMemsetAsync(buf2, 0, (size_t)N1v * 32 * sizeof(float), 0);
    spconv_mma<32, 32, 32, 3><<<dim3((M2v + 127) / 128, 1, K5v), 256>>>(
        buf1, wf + (size_t)OFF_W1B * 8, km1b_in, km1b_out, buf2, M2v);
    cudaMemsetAsync(gsum, 0, 256 * sizeof(float), 0);
    cudaMemsetAsync(gsq, 0, 256 * sizeof(float), 0);
    bn_stats4<32><<<SG, 256>>>(buf2, N1v);
    bn_relu4_kernel<<<(N1v * 8 + 255) / 256, 256>>>(buf2, buf1, bn1b_g, bn1b_b, 1.0f / N1v, N1v * 8, 7);

    // ---- enc1c: conv(32->32, k5) + BN + relu -> x_e1 ----
    cudaMemsetAsync(buf2, 0, (size_t)N1v * 32 * sizeof(float), 0);
    spconv_mma<32, 32, 32, 3><<<dim3((M2v + 127) / 128, 1, K5v), 256>>>(
        buf1, wf + (size_t)OFF_W1C * 8, km1c_in, km1c_out, buf2, M2v);
    cudaMemsetAsync(gsum, 0, 256 * sizeof(float), 0);
    cudaMemsetAsync(gsq, 0, 256 * sizeof(float), 0);
    bn_stats4<32><<<SG, 256>>>(buf2, N1v);
    bn_relu4_kernel<<<(N1v * 8 + 255) / 256, 256>>>(buf2, x_e1, bn1c_g, bn1c_b, 1.0f / N1v, N1v * 8, 7);

    // ---- conv2: conv(32->64, k3), no activation ----
    cudaMemsetAsync(buf3, 0, (size_t)N2v * 64 * sizeof(float), 0);
    spconv_mma<32, 64, 64, 3><<<dim3((M3v + 127) / 128, 1, K3v), 256>>>(
        x_e1, wf + (size_t)OFF_W2 * 8, km2_in, km2_out, buf3, M3v);

    // ---- enc2a: conv(64->128, k3) + BN + relu ----
    cudaMemsetAsync(buf4, 0, (size_t)N2v * 128 * sizeof(float), 0);
    spconv_mma<64, 128, 128, 2><<<dim3((M4v + 127) / 128, 1, K3v), 256>>>(
        buf3, wf + (size_t)OFF_W3A * 8, km3a_in, km3a_out, buf4, M4v);
    cudaMemsetAsync(gsum, 0, 256 * sizeof(float), 0);
    cudaMemsetAsync(gsq, 0, 256 * sizeof(float), 0);
    bn_stats4<128><<<SG, 256>>>(buf4, N2v);
    bn_relu4_kernel<<<(N2v * 32 + 255) / 256, 256>>>(buf4, buf4, bn3a_g, bn3a_b, 1.0f / N2v, N2v * 32, 31);

    // ---- enc2b: conv(128->256, k3) + BN + relu -> x_e2 ----
    cudaMemsetAsync(buf5, 0, (size_t)N2v * 256 * sizeof(float), 0);
    spconv_b64<<<dim3((M4v + 63) / 64, 1, K3v), 256>>>(
        buf4, wf + (size_t)OFF_W3B * 8, km3b_in, km3b_out, buf5, M4v);
    cudaMemsetAsync(gsum, 0, 256 * sizeof(float), 0);
    cudaMemsetAsync(gsq, 0, 256 * sizeof(float), 0);
    bn_stats4<256><<<SG, 256>>>(buf5, N2v);
    bn_relu4_kernel<<<(N2v * 64 + 255) / 256, 256>>>(buf5, x_e2, bn3b_g, bn3b_b, 1.0f / N2v, N2v * 64, 63);
}

// round 16
// speedup vs baseline: 1.4550x; 1.0059x over previous
#include <cuda_runtime.h>
#include <cuda_bf16.h>
#include <cstdint>

// ---------------- problem constants ----------------
#define N0v 200000
#define N1v 100000
#define N2v 80000
#define K5v 125
#define K3v 27
#define M1v 20000
#define M2v 20000
#define M3v 30000
#define M4v 20000
#define EPSv 1e-5f

// ---------------- scratch ----------------
__device__ float g_buf1[N1v * 32];
__device__ float g_buf2[N1v * 32];
__device__ float g_buf3[N2v * 64];
__device__ float g_buf4[N2v * 128];
__device__ float g_buf5[N2v * 256];
__device__ float g_sum[256];
__device__ float g_sumsq[256];

#define OFF_W1B 0
#define OFF_W1C 32000
#define OFF_W2  64000
#define OFF_W3A 77824
#define OFF_W3B 133120
#define WFRAG_U4 354304
__device__ __align__(16) __nv_bfloat16 g_wfrag[WFRAG_U4 * 8];

// ---------------- helpers ----------------
__device__ __forceinline__ void red4(float* p, float a, float b, float c, float d) {
    asm volatile("red.global.add.v4.f32 [%0], {%1,%2,%3,%4};"
                 :: "l"(p), "f"(a), "f"(b), "f"(c), "f"(d) : "memory");
}

__device__ __forceinline__ void mma16(float* d, const uint32_t* a, uint32_t b0, uint32_t b1) {
    asm volatile(
        "mma.sync.aligned.m16n8k16.row.col.f32.bf16.bf16.f32 "
        "{%0,%1,%2,%3}, {%4,%5,%6,%7}, {%8,%9}, {%0,%1,%2,%3};"
        : "+f"(d[0]), "+f"(d[1]), "+f"(d[2]), "+f"(d[3])
        : "r"(a[0]), "r"(a[1]), "r"(a[2]), "r"(a[3]), "r"(b0), "r"(b1));
}

__device__ __forceinline__ void ldsm4(uint32_t* r, uint32_t addr) {
    asm volatile("ldmatrix.sync.aligned.m8n8.x4.shared.b16 {%0,%1,%2,%3}, [%4];"
                 : "=r"(r[0]), "=r"(r[1]), "=r"(r[2]), "=r"(r[3]) : "r"(addr));
}

__device__ __forceinline__ void split4(float4 v, uint2* dh, uint2* dl) {
    __nv_bfloat162 h01 = __floats2bfloat162_rn(v.x, v.y);
    __nv_bfloat162 h23 = __floats2bfloat162_rn(v.z, v.w);
    __nv_bfloat162 l01 = __floats2bfloat162_rn(
        v.x - __bfloat162float(h01.x), v.y - __bfloat162float(h01.y));
    __nv_bfloat162 l23 = __floats2bfloat162_rn(
        v.z - __bfloat162float(h23.x), v.w - __bfloat162float(h23.y));
    *dh = make_uint2(*reinterpret_cast<uint32_t*>(&h01), *reinterpret_cast<uint32_t*>(&h23));
    *dl = make_uint2(*reinterpret_cast<uint32_t*>(&l01), *reinterpret_cast<uint32_t*>(&l23));
}

// ---------------- weight prep ----------------
__device__ __forceinline__ void wpack(float v, int e, int CIN, int COUT,
                                      __nv_bfloat16* frag) {
    int per = CIN * COUT;
    int k = e / per;
    int r = e - k * per;
    int ci = r / COUT;
    int co = r - ci * COUT;
    __nv_bfloat16 h = __float2bfloat16(v);
    __nv_bfloat16 l = __float2bfloat16(v - __bfloat162float(h));
    int lane = ((co & 7) << 2) | ((ci & 7) >> 1);
    size_t f4 = (((size_t)k * (CIN >> 4) + (ci >> 4)) * (COUT >> 3) + (co >> 3)) * 32 + lane;
    int within = ci & 15;
    int slot = ((within >> 3) << 1) | (within & 1);
    frag[f4 * 8 + slot] = h;
    frag[f4 * 8 + 4 + slot] = l;
}

__global__ void wprep_all(const float* __restrict__ w1b, const float* __restrict__ w1c,
                          const float* __restrict__ w2, const float* __restrict__ w3a,
                          const float* __restrict__ w3b, __nv_bfloat16* __restrict__ frag) {
    int g = blockIdx.x * blockDim.x + threadIdx.x;
    if (g < 128000)       wpack(w1b[g], g, 32, 32, frag + (size_t)OFF_W1B * 8);
    else if (g < 256000)  wpack(w1c[g - 128000], g - 128000, 32, 32, frag + (size_t)OFF_W1C * 8);
    else if (g < 311296)  wpack(w2[g - 256000], g - 256000, 32, 64, frag + (size_t)OFF_W2 * 8);
    else if (g < 532480)  wpack(w3a[g - 311296], g - 311296, 64, 128, frag + (size_t)OFF_W3A * 8);
    else if (g < 1417216) wpack(w3b[g - 532480], g - 532480, 128, 256, frag + (size_t)OFF_W3B * 8);
}

// ---------------- conv1a: CIN=1, 8 lanes per (k,m) pair ----------------
__global__ void conv1a_kernel(const float* __restrict__ x, const float* __restrict__ w,
                              const int* __restrict__ in_idx, const int* __restrict__ out_idx,
                              float* __restrict__ out, int total, int M) {
    int gid = blockIdx.x * blockDim.x + threadIdx.x;
    int pair = gid >> 3;
    if (pair >= total) return;
    int g = gid & 7;
    int k = pair / M;
    float v = x[in_idx[pair]];
    float4 wv = *reinterpret_cast<const float4*>(w + k * 32 + g * 4);
    float* dst = out + (size_t)out_idx[pair] * 32 + g * 4;
    red4(dst, v * wv.x, v * wv.y, v * wv.z, v * wv.w);
}

// ---------------- gather-MMA-scatter: coalesced 8-lane-per-row gather ----------------
template<int CIN, int COUT, int BN, int MINB>
__global__ __launch_bounds__(256, MINB)
void spconv_mma(const float* __restrict__ feats, const __nv_bfloat16* __restrict__ wfrag,
                const int* __restrict__ in_idx, const int* __restrict__ out_idx,
                float* __restrict__ out, int M) {
    constexpr int NT  = BN / 8;
    constexpr int NTG = COUT / 8;
    constexpr int NCH = CIN / 32;
    constexpr uint32_t BUFSTRIDE = 128 * 20 * 4;

    __shared__ uint32_t As_h[2][128][20];
    __shared__ uint32_t As_l[2][128][20];

    const int k    = blockIdx.z;
    const int m0   = blockIdx.x * 128;
    const int n0   = blockIdx.y * BN;
    const int tid  = threadIdx.x;
    const int wid  = tid >> 5;
    const int lane = tid & 31;

    // gather mapping: 8 lanes per row; each thread covers 4 rows spaced 32 apart
    const int rowq = tid >> 3;    // 0..31
    const int colq = tid & 7;     // float4 index within 32-float row
    int frows[4];
#pragma unroll
    for (int j = 0; j < 4; j++) {
        int mm = m0 + rowq + j * 32;
        frows[j] = (mm < M) ? in_idx[k * M + mm] : -1;
    }

    float acc[NT][4];
#pragma unroll
    for (int nt = 0; nt < NT; nt++) {
        acc[nt][0] = 0.f; acc[nt][1] = 0.f; acc[nt][2] = 0.f; acc[nt][3] = 0.f;
    }

    const uint4* wbase = reinterpret_cast<const uint4*>(wfrag)
                       + ((size_t)k * (CIN >> 4)) * NTG * 32;
    const int gr = lane >> 2;
    const int gc = lane & 3;
    const int r0 = wid * 16 + gr;

    const int lrow = wid * 16 + (lane & 15);
    const uint32_t lchunk = (lane >> 4) << 4;
    const uint32_t admH = (uint32_t)__cvta_generic_to_shared(&As_h[0][lrow][0]) + lchunk;
    const uint32_t admL = (uint32_t)__cvta_generic_to_shared(&As_l[0][lrow][0]) + lchunk;

    float4 pf[4];
    // prologue: gather chunk 0 (coalesced: 8 lanes cover one 128B row)
#pragma unroll
    for (int j = 0; j < 4; j++) {
        if (frows[j] >= 0)
            pf[j] = *reinterpret_cast<const float4*>(
                feats + (size_t)frows[j] * CIN + colq * 4);
        else
            pf[j] = make_float4(0.f, 0.f, 0.f, 0.f);
    }
    {
#pragma unroll
        for (int j = 0; j < 4; j++) {
            int row = rowq + j * 32;
            split4(pf[j],
                   reinterpret_cast<uint2*>(&As_h[0][row][colq * 2]),
                   reinterpret_cast<uint2*>(&As_l[0][row][colq * 2]));
        }
    }
    __syncthreads();

#pragma unroll
    for (int c = 0; c < NCH; c++) {
        const int cb = c & 1;
        // prefetch next chunk
        if (c + 1 < NCH) {
#pragma unroll
            for (int j = 0; j < 4; j++) {
                if (frows[j] >= 0)
                    pf[j] = *reinterpret_cast<const float4*>(
                        feats + (size_t)frows[j] * CIN + (c + 1) * 32 + colq * 4);
                else
                    pf[j] = make_float4(0.f, 0.f, 0.f, 0.f);
            }
        }

#pragma unroll
        for (int s = 0; s < 2; s++) {
            uint32_t aH[4], aL[4];
            const uint32_t off = cb * BUFSTRIDE + s * 32;
            ldsm4(aH, admH + off);
            ldsm4(aL, admL + off);

            const uint4* wrow = wbase + ((size_t)(c * 2 + s) * NTG + (n0 >> 3)) * 32 + lane;
#pragma unroll
            for (int ng = 0; ng < NT; ng += 4) {
                uint4 b0 = wrow[(ng + 0) * 32];
                uint4 b1 = wrow[(ng + 1) * 32];
                uint4 b2 = wrow[(ng + 2) * 32];
                uint4 b3 = wrow[(ng + 3) * 32];
                mma16(acc[ng + 0], aH, b0.x, b0.y);
                mma16(acc[ng + 1], aH, b1.x, b1.y);
                mma16(acc[ng + 2], aH, b2.x, b2.y);
                mma16(acc[ng + 3], aH, b3.x, b3.y);
                mma16(acc[ng + 0], aL, b0.x, b0.y);
                mma16(acc[ng + 1], aL, b1.x, b1.y);
                mma16(acc[ng + 2], aL, b2.x, b2.y);
                mma16(acc[ng + 3], aL, b3.x, b3.y);
                mma16(acc[ng + 0], aH, b0.z, b0.w);
                mma16(acc[ng + 1], aH, b1.z, b1.w);
                mma16(acc[ng + 2], aH, b2.z, b2.w);
                mma16(acc[ng + 3], aH, b3.z, b3.w);
            }
        }

        if (c + 1 < NCH) {
            const int nb = (c + 1) & 1;
#pragma unroll
            for (int j = 0; j < 4; j++) {
                int row = rowq + j * 32;
                split4(pf[j],
                       reinterpret_cast<uint2*>(&As_h[nb][row][colq * 2]),
                       reinterpret_cast<uint2*>(&As_l[nb][row][colq * 2]));
            }
            __syncthreads();
        }
    }

    const int mA = m0 + r0;
    const int mB = mA + 8;
    const int oA = (mA < M) ? out_idx[k * M + mA] : -1;
    const int oB = (mB < M) ? out_idx[k * M + mB] : -1;
    float* dA0 = out + (oA >= 0 ? (size_t)oA * COUT : 0) + n0;
    float* dB0 = out + (oB >= 0 ? (size_t)oB * COUT : 0) + n0;
    const bool even = (gc & 1) == 0;

#pragma unroll
    for (int nt = 0; nt < NT; nt += 2) {
        float sA0 = even ? acc[nt + 1][0] : acc[nt][0];
        float sA1 = even ? acc[nt + 1][1] : acc[nt][1];
        float sB0 = even ? acc[nt + 1][2] : acc[nt][2];
        float sB1 = even ? acc[nt + 1][3] : acc[nt][3];
        float rA0 = __shfl_xor_sync(0xffffffffu, sA0, 1);
        float rA1 = __shfl_xor_sync(0xffffffffu, sA1, 1);
        float rB0 = __shfl_xor_sync(0xffffffffu, sB0, 1);
        float rB1 = __shfl_xor_sync(0xffffffffu, sB1, 1);
        int myt = even ? nt : nt + 1;
        int cbase = myt * 8 + (even ? 2 * gc : 2 * gc - 2);
        float a0 = even ? acc[nt][0] : rA0;
        float a1 = even ? acc[nt][1] : rA1;
        float a2 = even ? rA0 : acc[nt + 1][0];
        float a3 = even ? rA1 : acc[nt + 1][1];
        float b0 = even ? acc[nt][2] : rB0;
        float b1 = even ? acc[nt][3] : rB1;
        float b2 = even ? rB0 : acc[nt + 1][2];
        float b3 = even ? rB1 : acc[nt + 1][3];
        if (oA >= 0) red4(dA0 + cbase, a0, a1, a2, a3);
        if (oB >= 0) red4(dB0 + cbase, b0, b1, b2, b3);
    }
}

// ---------------- conv3b: BM=64, full COUT=256 per CTA (R13 exact, untouched) ----------------
__global__ __launch_bounds__(256, 2)
void spconv_b64(const float* __restrict__ feats, const __nv_bfloat16* __restrict__ wfrag,
                const int* __restrict__ in_idx, const int* __restrict__ out_idx,
                float* __restrict__ out, int M) {
    constexpr int CIN = 128, COUT = 256;
    constexpr int NT  = 16;
    constexpr int NTG = COUT / 8;
    constexpr int NCH = CIN / 32;
    constexpr uint32_t BUFSTRIDE = 64 * 20 * 4;

    __shared__ uint32_t As_h[2][64][20];
    __shared__ uint32_t As_l[2][64][20];

    const int k    = blockIdx.z;
    const int m0   = blockIdx.x * 64;
    const int tid  = threadIdx.x;
    const int wid  = tid >> 5;
    const int lane = tid & 31;

    const int mrow = tid >> 2;
    const int q    = tid & 3;
    const int m    = m0 + mrow;
    const int frow = (m < M) ? in_idx[k * M + m] : -1;
    const float* fbase = (frow >= 0) ? (feats + (size_t)frow * CIN + q * 8) : feats;

    const int mt = wid & 3;
    const int nh = wid >> 2;

    float acc[NT][4];
#pragma unroll
    for (int nt = 0; nt < NT; nt++) {
        acc[nt][0] = 0.f; acc[nt][1] = 0.f; acc[nt][2] = 0.f; acc[nt][3] = 0.f;
    }

    const uint4* wbase = reinterpret_cast<const uint4*>(wfrag)
                       + ((size_t)k * (CIN >> 4)) * NTG * 32;
    const int gr = lane >> 2;
    const int gc = lane & 3;

    const int lrow = mt * 16 + (lane & 15);
    const uint32_t lchunk = (lane >> 4) << 4;
    const uint32_t admH = (uint32_t)__cvta_generic_to_shared(&As_h[0][lrow][0]) + lchunk;
    const uint32_t admL = (uint32_t)__cvta_generic_to_shared(&As_l[0][lrow][0]) + lchunk;

    float4 pf[2];
    if (frow >= 0) {
        const float4* s = reinterpret_cast<const float4*>(fbase);
        pf[0] = s[0]; pf[1] = s[1];
    }
    {
        uint2* dh = reinterpret_cast<uint2*>(&As_h[0][mrow][q * 4]);
        uint2* dl = reinterpret_cast<uint2*>(&As_l[0][mrow][q * 4]);
        if (frow >= 0) {
            split4(pf[0], dh, dl);
            split4(pf[1], dh + 1, dl + 1);
        } else {
            uint2 z = make_uint2(0u, 0u);
            dh[0] = z; dh[1] = z; dl[0] = z; dl[1] = z;
        }
    }
    __syncthreads();

#pragma unroll
    for (int c = 0; c < NCH; c++) {
        const int cb = c & 1;
        if (c + 1 < NCH && frow >= 0) {
            const float4* s = reinterpret_cast<const float4*>(fbase + (c + 1) * 32);
            pf[0] = s[0]; pf[1] = s[1];
        }

#pragma unroll
        for (int s = 0; s < 2; s++) {
            uint32_t aH[4], aL[4];
            const uint32_t off = cb * BUFSTRIDE + s * 32;
            ldsm4(aH, admH + off);
            ldsm4(aL, admL + off);

            const uint4* wrow = wbase + ((size_t)(c * 2 + s) * NTG + nh * 16) * 32 + lane;
#pragma unroll
            for (int ng = 0; ng < NT; ng += 4) {
                uint4 b0 = wrow[(ng + 0) * 32];
                uint4 b1 = wrow[(ng + 1) * 32];
                uint4 b2 = wrow[(ng + 2) * 32];
                uint4 b3 = wrow[(ng + 3) * 32];
                mma16(acc[ng + 0], aH, b0.x, b0.y);
                mma16(acc[ng + 1], aH, b1.x, b1.y);
                mma16(acc[ng + 2], aH, b2.x, b2.y);
                mma16(acc[ng + 3], aH, b3.x, b3.y);
                mma16(acc[ng + 0], aL, b0.x, b0.y);
                mma16(acc[ng + 1], aL, b1.x, b1.y);
                mma16(acc[ng + 2], aL, b2.x, b2.y);
                mma16(acc[ng + 3], aL, b3.x, b3.y);
                mma16(acc[ng + 0], aH, b0.z, b0.w);
                mma16(acc[ng + 1], aH, b1.z, b1.w);
                mma16(acc[ng + 2], aH, b2.z, b2.w);
                mma16(acc[ng + 3], aH, b3.z, b3.w);
            }
        }

        if (c + 1 < NCH) {
            const int nb = (c + 1) & 1;
            uint2* dh = reinterpret_cast<uint2*>(&As_h[nb][mrow][q * 4]);
            uint2* dl = reinterpret_cast<uint2*>(&As_l[nb][mrow][q * 4]);
            if (frow >= 0) {
                split4(pf[0], dh, dl);
                split4(pf[1], dh + 1, dl + 1);
            } else {
                uint2 z = make_uint2(0u, 0u);
                dh[0] = z; dh[1] = z; dl[0] = z; dl[1] = z;
            }
            __syncthreads();
        }
    }

    const int mA = m0 + mt * 16 + gr;
    const int mB = mA + 8;
    const int oA = (mA < M) ? out_idx[k * M + mA] : -1;
    const int oB = (mB < M) ? out_idx[k * M + mB] : -1;
    float* dA0 = out + (oA >= 0 ? (size_t)oA * COUT : 0) + nh * 128;
    float* dB0 = out + (oB >= 0 ? (size_t)oB * COUT : 0) + nh * 128;
    const bool even = (gc & 1) == 0;

#pragma unroll
    for (int nt = 0; nt < NT; nt += 2) {
        float sA0 = even ? acc[nt + 1][0] : acc[nt][0];
        float sA1 = even ? acc[nt + 1][1] : acc[nt][1];
        float sB0 = even ? acc[nt + 1][2] : acc[nt][2];
        float sB1 = even ? acc[nt + 1][3] : acc[nt][3];
        float rA0 = __shfl_xor_sync(0xffffffffu, sA0, 1);
        float rA1 = __shfl_xor_sync(0xffffffffu, sA1, 1);
        float rB0 = __shfl_xor_sync(0xffffffffu, sB0, 1);
        float rB1 = __shfl_xor_sync(0xffffffffu, sB1, 1);
        int myt = even ? nt : nt + 1;
        int cbase = myt * 8 + (even ? 2 * gc : 2 * gc - 2);
        float a0 = even ? acc[nt][0] : rA0;
        float a1 = even ? acc[nt][1] : rA1;
        float a2 = even ? rA0 : acc[nt + 1][0];
        float a3 = even ? rA1 : acc[nt + 1][1];
        float b0 = even ? acc[nt][2] : rB0;
        float b1 = even ? acc[nt][3] : rB1;
        float b2 = even ? rB0 : acc[nt + 1][2];
        float b3 = even ? rB1 : acc[nt + 1][3];
        if (oA >= 0) red4(dA0 + cbase, a0, a1, a2, a3);
        if (oB >= 0) red4(dB0 + cbase, b0, b1, b2, b3);
    }
}

// ---------------- elementwise / BN kernels ----------------
__global__ void relu_kernel(float* __restrict__ x, int n4) {
    int i = blockIdx.x * blockDim.x + threadIdx.x;
    if (i >= n4) return;
    float4 v = reinterpret_cast<float4*>(x)[i];
    v.x = fmaxf(v.x, 0.f); v.y = fmaxf(v.y, 0.f);
    v.z = fmaxf(v.z, 0.f); v.w = fmaxf(v.w, 0.f);
    reinterpret_cast<float4*>(x)[i] = v;
}

template<int C>
__global__ void bn_stats4(const float* __restrict__ x, int rows) {
    constexpr int CG = C / 4;
    constexpr int RPB = 256 / CG;
    const int cg  = threadIdx.x & (CG - 1);
    const int rsub = threadIdx.x / CG;
    float s0 = 0.f, s1 = 0.f, s2 = 0.f, s3 = 0.f;
    float q0 = 0.f, q1 = 0.f, q2 = 0.f, q3 = 0.f;
    for (int r = blockIdx.x * RPB + rsub; r < rows; r += gridDim.x * RPB) {
        float4 v = *reinterpret_cast<const float4*>(x + (size_t)r * C + cg * 4);
        s0 += v.x; q0 += v.x * v.x;
        s1 += v.y; q1 += v.y * v.y;
        s2 += v.z; q2 += v.z * v.z;
        s3 += v.w; q3 += v.w * v.w;
    }
    __shared__ float ss[256][4], sq[256][4];
    ss[threadIdx.x][0] = s0; ss[threadIdx.x][1] = s1;
    ss[threadIdx.x][2] = s2; ss[threadIdx.x][3] = s3;
    sq[threadIdx.x][0] = q0; sq[threadIdx.x][1] = q1;
    sq[threadIdx.x][2] = q2; sq[threadIdx.x][3] = q3;
    __syncthreads();
    if (threadIdx.x < C) {
        int mycg = threadIdx.x >> 2;
        int j = threadIdx.x & 3;
        float s = 0.f, q = 0.f;
        for (int t = mycg; t < 256; t += CG) { s += ss[t][j]; q += sq[t][j]; }
        atomicAdd(&g_sum[threadIdx.x], s);
        atomicAdd(&g_sumsq[threadIdx.x], q);
    }
}

__global__ void bn_relu4_kernel(const float* __restrict__ x, float* __restrict__ y,
                                const float* __restrict__ gg, const float* __restrict__ bb,
                                float invN, int total4, int cmask4) {
    int e = blockIdx.x * blockDim.x + threadIdx.x;
    if (e >= total4) return;
    int cg = e & cmask4;
    float4 v = reinterpret_cast<const float4*>(x)[e];
    int c = cg * 4;
    float m0 = g_sum[c] * invN,     m1 = g_sum[c + 1] * invN;
    float m2 = g_sum[c + 2] * invN, m3 = g_sum[c + 3] * invN;
    float s0 = rsqrtf(g_sumsq[c] * invN - m0 * m0 + EPSv) * gg[c];
    float s1 = rsqrtf(g_sumsq[c + 1] * invN - m1 * m1 + EPSv) * gg[c + 1];
    float s2 = rsqrtf(g_sumsq[c + 2] * invN - m2 * m2 + EPSv) * gg[c + 2];
    float s3 = rsqrtf(g_sumsq[c + 3] * invN - m3 * m3 + EPSv) * gg[c + 3];
    v.x = fmaxf((v.x - m0) * s0 + bb[c], 0.f);
    v.y = fmaxf((v.y - m1) * s1 + bb[c + 1], 0.f);
    v.z = fmaxf((v.z - m2) * s2 + bb[c + 2], 0.f);
    v.w = fmaxf((v.w - m3) * s3 + bb[c + 3], 0.f);
    reinterpret_cast<float4*>(y)[e] = v;
}

// ---------------- orchestration ----------------
extern "C" void kernel_launch(void* const* d_in, const int* in_sizes, int n_in,
                              void* d_out, int out_size) {
    const float* x_feats = (const float*)d_in[0];
    const float* w1a = (const float*)d_in[1];
    const float* w1b = (const float*)d_in[2];
    const float* w1c = (const float*)d_in[3];
    const float* w2  = (const float*)d_in[4];
    const float* w3a = (const float*)d_in[5];
    const float* w3b = (const float*)d_in[6];
    const float* bn1b_g = (const float*)d_in[7];
    const float* bn1b_b = (const float*)d_in[8];
    const float* bn1c_g = (const float*)d_in[9];
    const float* bn1c_b = (const float*)d_in[10];
    const float* bn3a_g = (const float*)d_in[11];
    const float* bn3a_b = (const float*)d_in[12];
    const float* bn3b_g = (const float*)d_in[13];
    const float* bn3b_b = (const float*)d_in[14];
    const int* km1a_in  = (const int*)d_in[15];
    const int* km1a_out = (const int*)d_in[16];
    const int* km1b_in  = (const int*)d_in[17];
    const int* km1b_out = (const int*)d_in[18];
    const int* km1c_in  = (const int*)d_in[19];
    const int* km1c_out = (const int*)d_in[20];
    const int* km2_in   = (const int*)d_in[21];
    const int* km2_out  = (const int*)d_in[22];
    const int* km3a_in  = (const int*)d_in[23];
    const int* km3a_out = (const int*)d_in[24];
    const int* km3b_in  = (const int*)d_in[25];
    const int* km3b_out = (const int*)d_in[26];

    float* out = (float*)d_out;
    float* x_e1 = out;
    float* x_e2 = out + (size_t)N1v * 32;

    float *buf1, *buf2, *buf3, *buf4, *buf5, *gsum, *gsq;
    __nv_bfloat16* wf;
    cudaGetSymbolAddress((void**)&buf1, g_buf1);
    cudaGetSymbolAddress((void**)&buf2, g_buf2);
    cudaGetSymbolAddress((void**)&buf3, g_buf3);
    cudaGetSymbolAddress((void**)&buf4, g_buf4);
    cudaGetSymbolAddress((void**)&buf5, g_buf5);
    cudaGetSymbolAddress((void**)&gsum, g_sum);
    cudaGetSymbolAddress((void**)&gsq, g_sumsq);
    cudaGetSymbolAddress((void**)&wf, g_wfrag);

    wprep_all<<<(1417216 + 255) / 256, 256>>>(w1b, w1c, w2, w3a, w3b, wf);

    const int SG = 1024;

    // ---- enc1a: conv(1->32, k5) + relu ----
    cudaMemsetAsync(buf1, 0, (size_t)N1v * 32 * sizeof(float), 0);
    {
        int total = K5v * M1v;
        conv1a_kernel<<<(total * 8 + 255) / 256, 256>>>(x_feats, w1a, km1a_in, km1a_out, buf1, total, M1v);
        relu_kernel<<<(N1v * 32 / 4 + 255) / 256, 256>>>(buf1, N1v * 32 / 4);
    }

    // ---- enc1b: conv(32->32, k5) + BN + relu ----
    cudaMemsetAsync(buf2, 0, (size_t)N1v * 32 * sizeof(float), 0);
    spconv_mma<32, 32, 32, 3><<<dim3((M2v + 127) / 128, 1, K5v), 256>>>(
        buf1, wf + (size_t)OFF_W1B * 8, km1b_in, km1b_out, buf2, M2v);
    cudaMemsetAsync(gsum, 0, 256 * sizeof(float), 0);
    cudaMemsetAsync(gsq, 0, 256 * sizeof(float), 0);
    bn_stats4<32><<<SG, 256>>>(buf2, N1v);
    bn_relu4_kernel<<<(N1v * 8 + 255) / 256, 256>>>(buf2, buf1, bn1b_g, bn1b_b, 1.0f / N1v, N1v * 8, 7);

    // ---- enc1c: conv(32->32, k5) + BN + relu -> x_e1 ----
    cudaMemsetAsync(buf2, 0, (size_t)N1v * 32 * sizeof(float), 0);
    spconv_mma<32, 32, 32, 3><<<dim3((M2v + 127) / 128, 1, K5v), 256>>>(
        buf1, wf + (size_t)OFF_W1C * 8, km1c_in, km1c_out, buf2, M2v);
    cudaMemsetAsync(gsum, 0, 256 * sizeof(float), 0);
    cudaMemsetAsync(gsq, 0, 256 * sizeof(float), 0);
    bn_stats4<32><<<SG, 256>>>(buf2, N1v);
    bn_relu4_kernel<<<(N1v * 8 + 255) / 256, 256>>>(buf2, x_e1, bn1c_g, bn1c_b, 1.0f / N1v, N1v * 8, 7);

    // ---- conv2: conv(32->64, k3), no activation ----
    cudaMemsetAsync(buf3, 0, (size_t)N2v * 64 * sizeof(float), 0);
    spconv_mma<32, 64, 64, 3><<<dim3((M3v + 127) / 128, 1, K3v), 256>>>(
        x_e1, wf + (size_t)OFF_W2 * 8, km2_in, km2_out, buf3, M3v);

    // ---- enc2a: conv(64->128, k3) + BN + relu ----
    cudaMemsetAsync(buf4, 0, (size_t)N2v * 128 * sizeof(float), 0);
    spconv_mma<64, 128, 128, 2><<<dim3((M4v + 127) / 128, 1, K3v), 256>>>(
        buf3, wf + (size_t)OFF_W3A * 8, km3a_in, km3a_out, buf4, M4v);
    cudaMemsetAsync(gsum, 0, 256 * sizeof(float), 0);
    cudaMemsetAsync(gsq, 0, 256 * sizeof(float), 0);
    bn_stats4<128><<<SG, 256>>>(buf4, N2v);
    bn_relu4_kernel<<<(N2v * 32 + 255) / 256, 256>>>(buf4, buf4, bn3a_g, bn3a_b, 1.0f / N2v, N2v * 32, 31);

    // ---- enc2b: conv(128->256, k3) + BN + relu -> x_e2 ----
    cudaMemsetAsync(buf5, 0, (size_t)N2v * 256 * sizeof(float), 0);
    spconv_b64<<<dim3((M4v + 63) / 64, 1, K3v), 256>>>(
        buf4, wf + (size_t)OFF_W3B * 8, km3b_in, km3b_out, buf5, M4v);
    cudaMemsetAsync(gsum, 0, 256 * sizeof(float), 0);
    cudaMemsetAsync(gsq, 0, 256 * sizeof(float), 0);
    bn_stats4<256><<<SG, 256>>>(buf5, N2v);
    bn_relu4_kernel<<<(N2v * 64 + 255) / 256, 256>>>(buf5, x_e2, bn3b_g, bn3b_b, 1.0f / N2v, N2v * 64, 63);
}

// round 17
// speedup vs baseline: 1.5287x; 1.0507x over previous
#include <cuda_runtime.h>
#include <cuda_bf16.h>
#include <cstdint>

// ---------------- problem constants ----------------
#define N0v 200000
#define N1v 100000
#define N2v 80000
#define K5v 125
#define K3v 27
#define M1v 20000
#define M2v 20000
#define M3v 30000
#define M4v 20000
#define EPSv 1e-5f

// ---------------- scratch ----------------
__device__ float g_buf1[N1v * 32];
__device__ float g_buf2[N1v * 32];
__device__ float g_buf3[N2v * 64];
__device__ float g_buf4[N2v * 128];
__device__ float g_buf5[N2v * 256];
__device__ float g_sum[256];
__device__ float g_sumsq[256];

#define OFF_W1B 0
#define OFF_W1C 32000
#define OFF_W2  64000
#define OFF_W3A 77824
#define OFF_W3B 133120
#define WFRAG_U4 354304
__device__ __align__(16) __nv_bfloat16 g_wfrag[WFRAG_U4 * 8];

// ---------------- helpers ----------------
__device__ __forceinline__ void red4(float* p, float a, float b, float c, float d) {
    asm volatile("red.global.add.v4.f32 [%0], {%1,%2,%3,%4};"
                 :: "l"(p), "f"(a), "f"(b), "f"(c), "f"(d) : "memory");
}

__device__ __forceinline__ void mma16(float* d, const uint32_t* a, uint32_t b0, uint32_t b1) {
    asm volatile(
        "mma.sync.aligned.m16n8k16.row.col.f32.bf16.bf16.f32 "
        "{%0,%1,%2,%3}, {%4,%5,%6,%7}, {%8,%9}, {%0,%1,%2,%3};"
        : "+f"(d[0]), "+f"(d[1]), "+f"(d[2]), "+f"(d[3])
        : "r"(a[0]), "r"(a[1]), "r"(a[2]), "r"(a[3]), "r"(b0), "r"(b1));
}

__device__ __forceinline__ void ldsm4(uint32_t* r, uint32_t addr) {
    asm volatile("ldmatrix.sync.aligned.m8n8.x4.shared.b16 {%0,%1,%2,%3}, [%4];"
                 : "=r"(r[0]), "=r"(r[1]), "=r"(r[2]), "=r"(r[3]) : "r"(addr));
}

__device__ __forceinline__ void split4(float4 v, uint2* dh, uint2* dl) {
    __nv_bfloat162 h01 = __floats2bfloat162_rn(v.x, v.y);
    __nv_bfloat162 h23 = __floats2bfloat162_rn(v.z, v.w);
    __nv_bfloat162 l01 = __floats2bfloat162_rn(
        v.x - __bfloat162float(h01.x), v.y - __bfloat162float(h01.y));
    __nv_bfloat162 l23 = __floats2bfloat162_rn(
        v.z - __bfloat162float(h23.x), v.w - __bfloat162float(h23.y));
    *dh = make_uint2(*reinterpret_cast<uint32_t*>(&h01), *reinterpret_cast<uint32_t*>(&h23));
    *dl = make_uint2(*reinterpret_cast<uint32_t*>(&l01), *reinterpret_cast<uint32_t*>(&l23));
}

// ---------------- weight prep ----------------
__device__ __forceinline__ void wpack(float v, int e, int CIN, int COUT,
                                      __nv_bfloat16* frag) {
    int per = CIN * COUT;
    int k = e / per;
    int r = e - k * per;
    int ci = r / COUT;
    int co = r - ci * COUT;
    __nv_bfloat16 h = __float2bfloat16(v);
    __nv_bfloat16 l = __float2bfloat16(v - __bfloat162float(h));
    int lane = ((co & 7) << 2) | ((ci & 7) >> 1);
    size_t f4 = (((size_t)k * (CIN >> 4) + (ci >> 4)) * (COUT >> 3) + (co >> 3)) * 32 + lane;
    int within = ci & 15;
    int slot = ((within >> 3) << 1) | (within & 1);
    frag[f4 * 8 + slot] = h;
    frag[f4 * 8 + 4 + slot] = l;
}

__global__ void wprep_all(const float* __restrict__ w1b, const float* __restrict__ w1c,
                          const float* __restrict__ w2, const float* __restrict__ w3a,
                          const float* __restrict__ w3b, __nv_bfloat16* __restrict__ frag) {
    int g = blockIdx.x * blockDim.x + threadIdx.x;
    if (g < 128000)       wpack(w1b[g], g, 32, 32, frag + (size_t)OFF_W1B * 8);
    else if (g < 256000)  wpack(w1c[g - 128000], g - 128000, 32, 32, frag + (size_t)OFF_W1C * 8);
    else if (g < 311296)  wpack(w2[g - 256000], g - 256000, 32, 64, frag + (size_t)OFF_W2 * 8);
    else if (g < 532480)  wpack(w3a[g - 311296], g - 311296, 64, 128, frag + (size_t)OFF_W3A * 8);
    else if (g < 1417216) wpack(w3b[g - 532480], g - 532480, 128, 256, frag + (size_t)OFF_W3B * 8);
}

// ---------------- conv1a: CIN=1, 8 lanes per (k,m) pair ----------------
__global__ void conv1a_kernel(const float* __restrict__ x, const float* __restrict__ w,
                              const int* __restrict__ in_idx, const int* __restrict__ out_idx,
                              float* __restrict__ out, int total, int M) {
    int gid = blockIdx.x * blockDim.x + threadIdx.x;
    int pair = gid >> 3;
    if (pair >= total) return;
    int g = gid & 7;
    int k = pair / M;
    float v = x[in_idx[pair]];
    float4 wv = *reinterpret_cast<const float4*>(w + k * 32 + g * 4);
    float* dst = out + (size_t)out_idx[pair] * 32 + g * 4;
    red4(dst, v * wv.x, v * wv.y, v * wv.z, v * wv.w);
}

// ---------------- gather-MMA-scatter: coalesced 8-lane-per-row gather (R16 exact) ----------------
template<int CIN, int COUT, int BN, int MINB>
__global__ __launch_bounds__(256, MINB)
void spconv_mma(const float* __restrict__ feats, const __nv_bfloat16* __restrict__ wfrag,
                const int* __restrict__ in_idx, const int* __restrict__ out_idx,
                float* __restrict__ out, int M) {
    constexpr int NT  = BN / 8;
    constexpr int NTG = COUT / 8;
    constexpr int NCH = CIN / 32;
    constexpr uint32_t BUFSTRIDE = 128 * 20 * 4;

    __shared__ uint32_t As_h[2][128][20];
    __shared__ uint32_t As_l[2][128][20];

    const int k    = blockIdx.z;
    const int m0   = blockIdx.x * 128;
    const int n0   = blockIdx.y * BN;
    const int tid  = threadIdx.x;
    const int wid  = tid >> 5;
    const int lane = tid & 31;

    const int rowq = tid >> 3;
    const int colq = tid & 7;
    int frows[4];
#pragma unroll
    for (int j = 0; j < 4; j++) {
        int mm = m0 + rowq + j * 32;
        frows[j] = (mm < M) ? in_idx[k * M + mm] : -1;
    }

    float acc[NT][4];
#pragma unroll
    for (int nt = 0; nt < NT; nt++) {
        acc[nt][0] = 0.f; acc[nt][1] = 0.f; acc[nt][2] = 0.f; acc[nt][3] = 0.f;
    }

    const uint4* wbase = reinterpret_cast<const uint4*>(wfrag)
                       + ((size_t)k * (CIN >> 4)) * NTG * 32;
    const int gr = lane >> 2;
    const int gc = lane & 3;
    const int r0 = wid * 16 + gr;

    const int lrow = wid * 16 + (lane & 15);
    const uint32_t lchunk = (lane >> 4) << 4;
    const uint32_t admH = (uint32_t)__cvta_generic_to_shared(&As_h[0][lrow][0]) + lchunk;
    const uint32_t admL = (uint32_t)__cvta_generic_to_shared(&As_l[0][lrow][0]) + lchunk;

    float4 pf[4];
#pragma unroll
    for (int j = 0; j < 4; j++) {
        if (frows[j] >= 0)
            pf[j] = *reinterpret_cast<const float4*>(
                feats + (size_t)frows[j] * CIN + colq * 4);
        else
            pf[j] = make_float4(0.f, 0.f, 0.f, 0.f);
    }
    {
#pragma unroll
        for (int j = 0; j < 4; j++) {
            int row = rowq + j * 32;
            split4(pf[j],
                   reinterpret_cast<uint2*>(&As_h[0][row][colq * 2]),
                   reinterpret_cast<uint2*>(&As_l[0][row][colq * 2]));
        }
    }
    __syncthreads();

#pragma unroll
    for (int c = 0; c < NCH; c++) {
        const int cb = c & 1;
        if (c + 1 < NCH) {
#pragma unroll
            for (int j = 0; j < 4; j++) {
                if (frows[j] >= 0)
                    pf[j] = *reinterpret_cast<const float4*>(
                        feats + (size_t)frows[j] * CIN + (c + 1) * 32 + colq * 4);
                else
                    pf[j] = make_float4(0.f, 0.f, 0.f, 0.f);
            }
        }

#pragma unroll
        for (int s = 0; s < 2; s++) {
            uint32_t aH[4], aL[4];
            const uint32_t off = cb * BUFSTRIDE + s * 32;
            ldsm4(aH, admH + off);
            ldsm4(aL, admL + off);

            const uint4* wrow = wbase + ((size_t)(c * 2 + s) * NTG + (n0 >> 3)) * 32 + lane;
#pragma unroll
            for (int ng = 0; ng < NT; ng += 4) {
                uint4 b0 = wrow[(ng + 0) * 32];
                uint4 b1 = wrow[(ng + 1) * 32];
                uint4 b2 = wrow[(ng + 2) * 32];
                uint4 b3 = wrow[(ng + 3) * 32];
                mma16(acc[ng + 0], aH, b0.x, b0.y);
                mma16(acc[ng + 1], aH, b1.x, b1.y);
                mma16(acc[ng + 2], aH, b2.x, b2.y);
                mma16(acc[ng + 3], aH, b3.x, b3.y);
                mma16(acc[ng + 0], aL, b0.x, b0.y);
                mma16(acc[ng + 1], aL, b1.x, b1.y);
                mma16(acc[ng + 2], aL, b2.x, b2.y);
                mma16(acc[ng + 3], aL, b3.x, b3.y);
                mma16(acc[ng + 0], aH, b0.z, b0.w);
                mma16(acc[ng + 1], aH, b1.z, b1.w);
                mma16(acc[ng + 2], aH, b2.z, b2.w);
                mma16(acc[ng + 3], aH, b3.z, b3.w);
            }
        }

        if (c + 1 < NCH) {
            const int nb = (c + 1) & 1;
#pragma unroll
            for (int j = 0; j < 4; j++) {
                int row = rowq + j * 32;
                split4(pf[j],
                       reinterpret_cast<uint2*>(&As_h[nb][row][colq * 2]),
                       reinterpret_cast<uint2*>(&As_l[nb][row][colq * 2]));
            }
            __syncthreads();
        }
    }

    const int mA = m0 + r0;
    const int mB = mA + 8;
    const int oA = (mA < M) ? out_idx[k * M + mA] : -1;
    const int oB = (mB < M) ? out_idx[k * M + mB] : -1;
    float* dA0 = out + (oA >= 0 ? (size_t)oA * COUT : 0) + n0;
    float* dB0 = out + (oB >= 0 ? (size_t)oB * COUT : 0) + n0;
    const bool even = (gc & 1) == 0;

#pragma unroll
    for (int nt = 0; nt < NT; nt += 2) {
        float sA0 = even ? acc[nt + 1][0] : acc[nt][0];
        float sA1 = even ? acc[nt + 1][1] : acc[nt][1];
        float sB0 = even ? acc[nt + 1][2] : acc[nt][2];
        float sB1 = even ? acc[nt + 1][3] : acc[nt][3];
        float rA0 = __shfl_xor_sync(0xffffffffu, sA0, 1);
        float rA1 = __shfl_xor_sync(0xffffffffu, sA1, 1);
        float rB0 = __shfl_xor_sync(0xffffffffu, sB0, 1);
        float rB1 = __shfl_xor_sync(0xffffffffu, sB1, 1);
        int myt = even ? nt : nt + 1;
        int cbase = myt * 8 + (even ? 2 * gc : 2 * gc - 2);
        float a0 = even ? acc[nt][0] : rA0;
        float a1 = even ? acc[nt][1] : rA1;
        float a2 = even ? rA0 : acc[nt + 1][0];
        float a3 = even ? rA1 : acc[nt + 1][1];
        float b0 = even ? acc[nt][2] : rB0;
        float b1 = even ? acc[nt][3] : rB1;
        float b2 = even ? rB0 : acc[nt + 1][2];
        float b3 = even ? rB1 : acc[nt + 1][3];
        if (oA >= 0) red4(dA0 + cbase, a0, a1, a2, a3);
        if (oB >= 0) red4(dB0 + cbase, b0, b1, b2, b3);
    }
}

// ---------------- conv3b: BM=64, coalesced 8-lane-per-chunk gather ----------------
__global__ __launch_bounds__(256, 2)
void spconv_b64(const float* __restrict__ feats, const __nv_bfloat16* __restrict__ wfrag,
                const int* __restrict__ in_idx, const int* __restrict__ out_idx,
                float* __restrict__ out, int M) {
    constexpr int CIN = 128, COUT = 256;
    constexpr int NT  = 16;
    constexpr int NTG = COUT / 8;
    constexpr int NCH = CIN / 32;
    constexpr uint32_t BUFSTRIDE = 64 * 20 * 4;

    __shared__ uint32_t As_h[2][64][20];
    __shared__ uint32_t As_l[2][64][20];

    const int k    = blockIdx.z;
    const int m0   = blockIdx.x * 64;
    const int tid  = threadIdx.x;
    const int wid  = tid >> 5;
    const int lane = tid & 31;

    // coalesced gather: 8 lanes cover one contiguous 128B chunk of a row;
    // each thread covers 2 rows spaced 32 apart
    const int rowq = tid >> 3;    // 0..31
    const int colq = tid & 7;     // float4 index within the 32-float chunk
    int frows[2];
#pragma unroll
    for (int j = 0; j < 2; j++) {
        int mm = m0 + rowq + j * 32;
        frows[j] = (mm < M) ? in_idx[k * M + mm] : -1;
    }

    const int mt = wid & 3;
    const int nh = wid >> 2;

    float acc[NT][4];
#pragma unroll
    for (int nt = 0; nt < NT; nt++) {
        acc[nt][0] = 0.f; acc[nt][1] = 0.f; acc[nt][2] = 0.f; acc[nt][3] = 0.f;
    }

    const uint4* wbase = reinterpret_cast<const uint4*>(wfrag)
                       + ((size_t)k * (CIN >> 4)) * NTG * 32;
    const int gr = lane >> 2;
    const int gc = lane & 3;

    const int lrow = mt * 16 + (lane & 15);
    const uint32_t lchunk = (lane >> 4) << 4;
    const uint32_t admH = (uint32_t)__cvta_generic_to_shared(&As_h[0][lrow][0]) + lchunk;
    const uint32_t admL = (uint32_t)__cvta_generic_to_shared(&As_l[0][lrow][0]) + lchunk;

    float4 pf[2];
    // prologue: gather chunk 0
#pragma unroll
    for (int j = 0; j < 2; j++) {
        if (frows[j] >= 0)
            pf[j] = *reinterpret_cast<const float4*>(
                feats + (size_t)frows[j] * CIN + colq * 4);
        else
            pf[j] = make_float4(0.f, 0.f, 0.f, 0.f);
    }
    {
#pragma unroll
        for (int j = 0; j < 2; j++) {
            int row = rowq + j * 32;
            split4(pf[j],
                   reinterpret_cast<uint2*>(&As_h[0][row][colq * 2]),
                   reinterpret_cast<uint2*>(&As_l[0][row][colq * 2]));
        }
    }
    __syncthreads();

#pragma unroll
    for (int c = 0; c < NCH; c++) {
        const int cb = c & 1;
        if (c + 1 < NCH) {
#pragma unroll
            for (int j = 0; j < 2; j++) {
                if (frows[j] >= 0)
                    pf[j] = *reinterpret_cast<const float4*>(
                        feats + (size_t)frows[j] * CIN + (c + 1) * 32 + colq * 4);
                else
                    pf[j] = make_float4(0.f, 0.f, 0.f, 0.f);
            }
        }

#pragma unroll
        for (int s = 0; s < 2; s++) {
            uint32_t aH[4], aL[4];
            const uint32_t off = cb * BUFSTRIDE + s * 32;
            ldsm4(aH, admH + off);
            ldsm4(aL, admL + off);

            const uint4* wrow = wbase + ((size_t)(c * 2 + s) * NTG + nh * 16) * 32 + lane;
#pragma unroll
            for (int ng = 0; ng < NT; ng += 4) {
                uint4 b0 = wrow[(ng + 0) * 32];
                uint4 b1 = wrow[(ng + 1) * 32];
                uint4 b2 = wrow[(ng + 2) * 32];
                uint4 b3 = wrow[(ng + 3) * 32];
                mma16(acc[ng + 0], aH, b0.x, b0.y);
                mma16(acc[ng + 1], aH, b1.x, b1.y);
                mma16(acc[ng + 2], aH, b2.x, b2.y);
                mma16(acc[ng + 3], aH, b3.x, b3.y);
                mma16(acc[ng + 0], aL, b0.x, b0.y);
                mma16(acc[ng + 1], aL, b1.x, b1.y);
                mma16(acc[ng + 2], aL, b2.x, b2.y);
                mma16(acc[ng + 3], aL, b3.x, b3.y);
                mma16(acc[ng + 0], aH, b0.z, b0.w);
                mma16(acc[ng + 1], aH, b1.z, b1.w);
                mma16(acc[ng + 2], aH, b2.z, b2.w);
                mma16(acc[ng + 3], aH, b3.z, b3.w);
            }
        }

        if (c + 1 < NCH) {
            const int nb = (c + 1) & 1;
#pragma unroll
            for (int j = 0; j < 2; j++) {
                int row = rowq + j * 32;
                split4(pf[j],
                       reinterpret_cast<uint2*>(&As_h[nb][row][colq * 2]),
                       reinterpret_cast<uint2*>(&As_l[nb][row][colq * 2]));
            }
            __syncthreads();
        }
    }

    const int mA = m0 + mt * 16 + gr;
    const int mB = mA + 8;
    const int oA = (mA < M) ? out_idx[k * M + mA] : -1;
    const int oB = (mB < M) ? out_idx[k * M + mB] : -1;
    float* dA0 = out + (oA >= 0 ? (size_t)oA * COUT : 0) + nh * 128;
    float* dB0 = out + (oB >= 0 ? (size_t)oB * COUT : 0) + nh * 128;
    const bool even = (gc & 1) == 0;

#pragma unroll
    for (int nt = 0; nt < NT; nt += 2) {
        float sA0 = even ? acc[nt + 1][0] : acc[nt][0];
        float sA1 = even ? acc[nt + 1][1] : acc[nt][1];
        float sB0 = even ? acc[nt + 1][2] : acc[nt][2];
        float sB1 = even ? acc[nt + 1][3] : acc[nt][3];
        float rA0 = __shfl_xor_sync(0xffffffffu, sA0, 1);
        float rA1 = __shfl_xor_sync(0xffffffffu, sA1, 1);
        float rB0 = __shfl_xor_sync(0xffffffffu, sB0, 1);
        float rB1 = __shfl_xor_sync(0xffffffffu, sB1, 1);
        int myt = even ? nt : nt + 1;
        int cbase = myt * 8 + (even ? 2 * gc : 2 * gc - 2);
        float a0 = even ? acc[nt][0] : rA0;
        float a1 = even ? acc[nt][1] : rA1;
        float a2 = even ? rA0 : acc[nt + 1][0];
        float a3 = even ? rA1 : acc[nt + 1][1];
        float b0 = even ? acc[nt][2] : rB0;
        float b1 = even ? acc[nt][3] : rB1;
        float b2 = even ? rB0 : acc[nt + 1][2];
        float b3 = even ? rB1 : acc[nt + 1][3];
        if (oA >= 0) red4(dA0 + cbase, a0, a1, a2, a3);
        if (oB >= 0) red4(dB0 + cbase, b0, b1, b2, b3);
    }
}

// ---------------- elementwise / BN kernels ----------------
__global__ void relu_kernel(float* __restrict__ x, int n4) {
    int i = blockIdx.x * blockDim.x + threadIdx.x;
    if (i >= n4) return;
    float4 v = reinterpret_cast<float4*>(x)[i];
    v.x = fmaxf(v.x, 0.f); v.y = fmaxf(v.y, 0.f);
    v.z = fmaxf(v.z, 0.f); v.w = fmaxf(v.w, 0.f);
    reinterpret_cast<float4*>(x)[i] = v;
}

template<int C>
__global__ void bn_stats4(const float* __restrict__ x, int rows) {
    constexpr int CG = C / 4;
    constexpr int RPB = 256 / CG;
    const int cg  = threadIdx.x & (CG - 1);
    const int rsub = threadIdx.x / CG;
    float s0 = 0.f, s1 = 0.f, s2 = 0.f, s3 = 0.f;
    float q0 = 0.f, q1 = 0.f, q2 = 0.f, q3 = 0.f;
    for (int r = blockIdx.x * RPB + rsub; r < rows; r += gridDim.x * RPB) {
        float4 v = *reinterpret_cast<const float4*>(x + (size_t)r * C + cg * 4);
        s0 += v.x; q0 += v.x * v.x;
        s1 += v.y; q1 += v.y * v.y;
        s2 += v.z; q2 += v.z * v.z;
        s3 += v.w; q3 += v.w * v.w;
    }
    __shared__ float ss[256][4], sq[256][4];
    ss[threadIdx.x][0] = s0; ss[threadIdx.x][1] = s1;
    ss[threadIdx.x][2] = s2; ss[threadIdx.x][3] = s3;
    sq[threadIdx.x][0] = q0; sq[threadIdx.x][1] = q1;
    sq[threadIdx.x][2] = q2; sq[threadIdx.x][3] = q3;
    __syncthreads();
    if (threadIdx.x < C) {
        int mycg = threadIdx.x >> 2;
        int j = threadIdx.x & 3;
        float s = 0.f, q = 0.f;
        for (int t = mycg; t < 256; t += CG) { s += ss[t][j]; q += sq[t][j]; }
        atomicAdd(&g_sum[threadIdx.x], s);
        atomicAdd(&g_sumsq[threadIdx.x], q);
    }
}

__global__ void bn_relu4_kernel(const float* __restrict__ x, float* __restrict__ y,
                                const float* __restrict__ gg, const float* __restrict__ bb,
                                float invN, int total4, int cmask4) {
    int e = blockIdx.x * blockDim.x + threadIdx.x;
    if (e >= total4) return;
    int cg = e & cmask4;
    float4 v = reinterpret_cast<const float4*>(x)[e];
    int c = cg * 4;
    float m0 = g_sum[c] * invN,     m1 = g_sum[c + 1] * invN;
    float m2 = g_sum[c + 2] * invN, m3 = g_sum[c + 3] * invN;
    float s0 = rsqrtf(g_sumsq[c] * invN - m0 * m0 + EPSv) * gg[c];
    float s1 = rsqrtf(g_sumsq[c + 1] * invN - m1 * m1 + EPSv) * gg[c + 1];
    float s2 = rsqrtf(g_sumsq[c + 2] * invN - m2 * m2 + EPSv) * gg[c + 2];
    float s3 = rsqrtf(g_sumsq[c + 3] * invN - m3 * m3 + EPSv) * gg[c + 3];
    v.x = fmaxf((v.x - m0) * s0 + bb[c], 0.f);
    v.y = fmaxf((v.y - m1) * s1 + bb[c + 1], 0.f);
    v.z = fmaxf((v.z - m2) * s2 + bb[c + 2], 0.f);
    v.w = fmaxf((v.w - m3) * s3 + bb[c + 3], 0.f);
    reinterpret_cast<float4*>(y)[e] = v;
}

// ---------------- orchestration ----------------
extern "C" void kernel_launch(void* const* d_in, const int* in_sizes, int n_in,
                              void* d_out, int out_size) {
    const float* x_feats = (const float*)d_in[0];
    const float* w1a = (const float*)d_in[1];
    const float* w1b = (const float*)d_in[2];
    const float* w1c = (const float*)d_in[3];
    const float* w2  = (const float*)d_in[4];
    const float* w3a = (const float*)d_in[5];
    const float* w3b = (const float*)d_in[6];
    const float* bn1b_g = (const float*)d_in[7];
    const float* bn1b_b = (const float*)d_in[8];
    const float* bn1c_g = (const float*)d_in[9];
    const float* bn1c_b = (const float*)d_in[10];
    const float* bn3a_g = (const float*)d_in[11];
    const float* bn3a_b = (const float*)d_in[12];
    const float* bn3b_g = (const float*)d_in[13];
    const float* bn3b_b = (const float*)d_in[14];
    const int* km1a_in  = (const int*)d_in[15];
    const int* km1a_out = (const int*)d_in[16];
    const int* km1b_in  = (const int*)d_in[17];
    const int* km1b_out = (const int*)d_in[18];
    const int* km1c_in  = (const int*)d_in[19];
    const int* km1c_out = (const int*)d_in[20];
    const int* km2_in   = (const int*)d_in[21];
    const int* km2_out  = (const int*)d_in[22];
    const int* km3a_in  = (const int*)d_in[23];
    const int* km3a_out = (const int*)d_in[24];
    const int* km3b_in  = (const int*)d_in[25];
    const int* km3b_out = (const int*)d_in[26];

    float* out = (float*)d_out;
    float* x_e1 = out;
    float* x_e2 = out + (size_t)N1v * 32;

    float *buf1, *buf2, *buf3, *buf4, *buf5, *gsum, *gsq;
    __nv_bfloat16* wf;
    cudaGetSymbolAddress((void**)&buf1, g_buf1);
    cudaGetSymbolAddress((void**)&buf2, g_buf2);
    cudaGetSymbolAddress((void**)&buf3, g_buf3);
    cudaGetSymbolAddress((void**)&buf4, g_buf4);
    cudaGetSymbolAddress((void**)&buf5, g_buf5);
    cudaGetSymbolAddress((void**)&gsum, g_sum);
    cudaGetSymbolAddress((void**)&gsq, g_sumsq);
    cudaGetSymbolAddress((void**)&wf, g_wfrag);

    wprep_all<<<(1417216 + 255) / 256, 256>>>(w1b, w1c, w2, w3a, w3b, wf);

    const int SG = 1024;

    // ---- enc1a: conv(1->32, k5) + relu ----
    cudaMemsetAsync(buf1, 0, (size_t)N1v * 32 * sizeof(float), 0);
    {
        int total = K5v * M1v;
        conv1a_kernel<<<(total * 8 + 255) / 256, 256>>>(x_feats, w1a, km1a_in, km1a_out, buf1, total, M1v);
        relu_kernel<<<(N1v * 32 / 4 + 255) / 256, 256>>>(buf1, N1v * 32 / 4);
    }

    // ---- enc1b: conv(32->32, k5) + BN + relu ----
    cudaMemsetAsync(buf2, 0, (size_t)N1v * 32 * sizeof(float), 0);
    spconv_mma<32, 32, 32, 3><<<dim3((M2v + 127) / 128, 1, K5v), 256>>>(
        buf1, wf + (size_t)OFF_W1B * 8, km1b_in, km1b_out, buf2, M2v);
    cudaMemsetAsync(gsum, 0, 256 * sizeof(float), 0);
    cudaMemsetAsync(gsq, 0, 256 * sizeof(float), 0);
    bn_stats4<32><<<SG, 256>>>(buf2, N1v);
    bn_relu4_kernel<<<(N1v * 8 + 255) / 256, 256>>>(buf2, buf1, bn1b_g, bn1b_b, 1.0f / N1v, N1v * 8, 7);

    // ---- enc1c: conv(32->32, k5) + BN + relu -> x_e1 ----
    cudaMemsetAsync(buf2, 0, (size_t)N1v * 32 * sizeof(float), 0);
    spconv_mma<32, 32, 32, 3><<<dim3((M2v + 127) / 128, 1, K5v), 256>>>(
        buf1, wf + (size_t)OFF_W1C * 8, km1c_in, km1c_out, buf2, M2v);
    cudaMemsetAsync(gsum, 0, 256 * sizeof(float), 0);
    cudaMemsetAsync(gsq, 0, 256 * sizeof(float), 0);
    bn_stats4<32><<<SG, 256>>>(buf2, N1v);
    bn_relu4_kernel<<<(N1v * 8 + 255) / 256, 256>>>(buf2, x_e1, bn1c_g, bn1c_b, 1.0f / N1v, N1v * 8, 7);

    // ---- conv2: conv(32->64, k3), no activation ----
    cudaMemsetAsync(buf3, 0, (size_t)N2v * 64 * sizeof(float), 0);
    spconv_mma<32, 64, 64, 3><<<dim3((M3v + 127) / 128, 1, K3v), 256>>>(
        x_e1, wf + (size_t)OFF_W2 * 8, km2_in, km2_out, buf3, M3v);

    // ---- enc2a: conv(64->128, k3) + BN + relu ----
    cudaMemsetAsync(buf4, 0, (size_t)N2v * 128 * sizeof(float), 0);
    spconv_mma<64, 128, 128, 2><<<dim3((M4v + 127) / 128, 1, K3v), 256>>>(
        buf3, wf + (size_t)OFF_W3A * 8, km3a_in, km3a_out, buf4, M4v);
    cudaMemsetAsync(gsum, 0, 256 * sizeof(float), 0);
    cudaMemsetAsync(gsq, 0, 256 * sizeof(float), 0);
    bn_stats4<128><<<SG, 256>>>(buf4, N2v);
    bn_relu4_kernel<<<(N2v * 32 + 255) / 256, 256>>>(buf4, buf4, bn3a_g, bn3a_b, 1.0f / N2v, N2v * 32, 31);

    // ---- enc2b: conv(128->256, k3) + BN + relu -> x_e2 ----
    cudaMemsetAsync(buf5, 0, (size_t)N2v * 256 * sizeof(float), 0);
    spconv_b64<<<dim3((M4v + 63) / 64, 1, K3v), 256>>>(
        buf4, wf + (size_t)OFF_W3B * 8, km3b_in, km3b_out, buf5, M4v);
    cudaMemsetAsync(gsum, 0, 256 * sizeof(float), 0);
    cudaMemsetAsync(gsq, 0, 256 * sizeof(float), 0);
    bn_stats4<256><<<SG, 256>>>(buf5, N2v);
    bn_relu4_kernel<<<(N2v * 64 + 255) / 256, 256>>>(buf5, x_e2, bn3b_g, bn3b_b, 1.0f / N2v, N2v * 64, 63);
}